// round 11
// baseline (speedup 1.0000x reference)
#include <cuda_runtime.h>
#include <cuda_bf16.h>
#include <math.h>
#include <stdint.h>

#define NB    2048
#define NBITS 64
#define NH    512
#define NHV   256

__device__ float g_sp[NB * NH];
__device__ float g_vs[NB * NHV];
__device__ uint8_t g_w2f8[NH * NH];     // W2^T e4m3 (x16)  [n][k]
__device__ uint8_t g_w3f8[NBITS * NH];  // W3^T e4m3 (x16)  [n3][k]

__device__ __forceinline__ uint32_t smem_u32(const void* p) {
    uint32_t a;
    asm("{ .reg .u64 t; cvta.to.shared.u64 t, %1; cvt.u32.u64 %0, t; }"
        : "=r"(a) : "l"(p));
    return a;
}
// d<15:8> = cvt(arg1), d<7:0> = cvt(arg2)  ->  pack(hi, lo): byte0 = lo
__device__ __forceinline__ uint16_t pack_e4m3x2(float lo, float hi) {
    uint16_t r;
    asm("cvt.rn.satfinite.e4m3x2.f32 %0, %1, %2;" : "=h"(r) : "f"(hi), "f"(lo));
    return r;
}
__device__ __forceinline__ uint32_t pack_e4m3x4(float a, float b, float c, float d) {
    uint16_t lo = pack_e4m3x2(a, b);   // byte0=a, byte1=b
    uint16_t hi = pack_e4m3x2(c, d);   // byte2=c, byte3=d
    uint32_t r;
    asm("mov.b32 %0, {%1, %2};" : "=r"(r) : "h"(lo), "h"(hi));
    return r;
}
__device__ __forceinline__ void cp16(uint32_t dst, const void* src) {
    asm volatile("cp.async.cg.shared.global [%0], [%1], 16;"
                 :: "r"(dst), "l"(src) : "memory");
}
__device__ __forceinline__ void mma_fp8(float* c, const uint32_t* a,
                                        uint32_t b0, uint32_t b1) {
    asm volatile("mma.sync.aligned.m16n8k32.row.col.f32.e4m3.e4m3.f32 "
                 "{%0,%1,%2,%3}, {%4,%5,%6,%7}, {%8,%9}, {%0,%1,%2,%3};"
                 : "+f"(c[0]), "+f"(c[1]), "+f"(c[2]), "+f"(c[3])
                 : "r"(a[0]), "r"(a[1]), "r"(a[2]), "r"(a[3]),
                   "r"(b0), "r"(b1));
}
__device__ __forceinline__ void ldm_x4(uint32_t* r, uint32_t addr) {
    asm volatile("ldmatrix.sync.aligned.m8n8.x4.shared.b16 {%0,%1,%2,%3}, [%4];"
                 : "=r"(r[0]), "=r"(r[1]), "=r"(r[2]), "=r"(r[3]) : "r"(addr));
}

#define SCALE     16.0f
#define INV_SC2   (1.0f / 256.0f)

// SMEM layout (fp8): h1 128 rows x 528 B; W2 tiles 128 x 144 B; W3 64 x 144 B
#define H1_OFF   0         // 67584
#define H1_STR   528
#define W2_OFF   67584     // 2 x 18432
#define W2_TILE  18432
#define W2_STR   144
#define W3_OFF   104448    // 9216
#define B2_OFF   113664    // 512 f32 (prescaled x16)
#define B3_OFF   115712    // 64 f32
#define AB_OFF   115968    // 128 f32
#define VS_OFF   116480    // 512 f32
#define VW2_OFF  118528    // 256 f32
#define SM_TOTAL 119552
#define LG_OFF   W2_OFF    // logits f32 (stride 68) after mainloop

// ---------------------------------------------------------------------------
// Fused aux: shift MLP (blocks 0..511) + W2 fp8 prep (512..767) + W3 (768..799)
// ---------------------------------------------------------------------------
__global__ __launch_bounds__(256) void aux_kernel(
    const float* __restrict__ shift_bits,
    const float* __restrict__ sd_w1, const float* __restrict__ sd_b1,
    const float* __restrict__ sd_w2, const float* __restrict__ sd_b2,
    const float* __restrict__ sd_w3, const float* __restrict__ sd_b3,
    const float* __restrict__ ix_w1, const float* __restrict__ v_w1,
    const float* __restrict__ ix_w2, const float* __restrict__ ix_w3)
{
    const int bid = blockIdx.x;
    const int t   = threadIdx.x;

    if (bid >= 512) {
        if (bid < 768) {                       // W2: transpose + scale + fp8
            int idx = (bid - 512) * 256 + t;   // 0..65535
            int n = idx >> 7, k4 = (idx & 127) * 4;
            float w0 = ix_w2[(k4 + 0) * NH + n] * SCALE;
            float w1 = ix_w2[(k4 + 1) * NH + n] * SCALE;
            float w2v = ix_w2[(k4 + 2) * NH + n] * SCALE;
            float w3v = ix_w2[(k4 + 3) * NH + n] * SCALE;
            ((uint32_t*)g_w2f8)[n * 128 + (idx & 127)] = pack_e4m3x4(w0, w1, w2v, w3v);
        } else {                               // W3
            int idx = (bid - 768) * 256 + t;   // 0..8191
            int n3 = idx >> 7, k4g = idx & 127;
            int k4 = k4g * 4;
            float w0 = ix_w3[(k4 + 0) * NBITS + n3] * SCALE;
            float w1 = ix_w3[(k4 + 1) * NBITS + n3] * SCALE;
            float w2v = ix_w3[(k4 + 2) * NBITS + n3] * SCALE;
            float w3v = ix_w3[(k4 + 3) * NBITS + n3] * SCALE;
            ((uint32_t*)g_w3f8)[n3 * 128 + k4g] = pack_e4m3x4(w0, w1, w2v, w3v);
        }
        return;
    }

    // ---- shift MLP, 4 batch rows per block ----
    const int ROWS = 4;
    __shared__ float xs[ROWS][NBITS];
    __shared__ float hs[ROWS][NH];
    __shared__ float gs[ROWS][NH];
    __shared__ float lgs[ROWS][NBITS];
    __shared__ float sms[ROWS][NBITS];

    const int b0 = bid * ROWS;

    for (int idx = t; idx < ROWS * NBITS; idx += 256) {
        int r = idx >> 6, k = idx & 63;
        xs[r][k] = shift_bits[(b0 + r) * NBITS + k];
    }
    __syncthreads();

    {   // layer 1
        const int j0 = t, j1 = t + 256;
        float a0[ROWS], a1[ROWS];
        #pragma unroll
        for (int r = 0; r < ROWS; r++) { a0[r] = 0.f; a1[r] = 0.f; }
        for (int k = 0; k < NBITS; k++) {
            float w0 = sd_w1[k * NH + j0];
            float w1 = sd_w1[k * NH + j1];
            #pragma unroll
            for (int r = 0; r < ROWS; r++) {
                a0[r] = fmaf(xs[r][k], w0, a0[r]);
                a1[r] = fmaf(xs[r][k], w1, a1[r]);
            }
        }
        float bb0 = sd_b1[j0], bb1 = sd_b1[j1];
        #pragma unroll
        for (int r = 0; r < ROWS; r++) {
            hs[r][j0] = fmaxf(a0[r] + bb0, 0.f);
            hs[r][j1] = fmaxf(a1[r] + bb1, 0.f);
        }
    }
    __syncthreads();

    {   // layer 2
        const int j0 = t, j1 = t + 256;
        float a0[ROWS], a1[ROWS];
        #pragma unroll
        for (int r = 0; r < ROWS; r++) { a0[r] = 0.f; a1[r] = 0.f; }
        for (int k = 0; k < NH; k++) {
            float w0 = sd_w2[k * NH + j0];
            float w1 = sd_w2[k * NH + j1];
            #pragma unroll
            for (int r = 0; r < ROWS; r++) {
                a0[r] = fmaf(hs[r][k], w0, a0[r]);
                a1[r] = fmaf(hs[r][k], w1, a1[r]);
            }
        }
        float bb0 = sd_b2[j0], bb1 = sd_b2[j1];
        #pragma unroll
        for (int r = 0; r < ROWS; r++) {
            gs[r][j0] = fmaxf(a0[r] + bb0, 0.f);
            gs[r][j1] = fmaxf(a1[r] + bb1, 0.f);
        }
    }
    __syncthreads();

    {   // layer 3
        int r = t >> 6, j = t & 63;
        float acc = 0.f;
        for (int k = 0; k < NH; k++)
            acc = fmaf(gs[r][k], sd_w3[k * NBITS + j], acc);
        lgs[r][j] = acc + sd_b3[j];
    }
    __syncthreads();

    {   // softmax over 64 (warps 0..3 -> rows)
        int wr = t >> 5, l = t & 31;
        if (wr < ROWS) {
            float v0 = lgs[wr][l], v1 = lgs[wr][l + 32];
            float m = fmaxf(v0, v1);
            #pragma unroll
            for (int o = 16; o > 0; o >>= 1) m = fmaxf(m, __shfl_xor_sync(0xffffffffu, m, o));
            float e0 = expf(v0 - m), e1 = expf(v1 - m);
            float s = e0 + e1;
            #pragma unroll
            for (int o = 16; o > 0; o >>= 1) s += __shfl_xor_sync(0xffffffffu, s, o);
            float inv = 1.f / s;
            sms[wr][l] = e0 * inv;
            sms[wr][l + 32] = e1 * inv;
        }
    }
    __syncthreads();

    {   // shift_part
        const int j0 = t, j1 = t + 256;
        float a0[ROWS], a1[ROWS];
        #pragma unroll
        for (int r = 0; r < ROWS; r++) { a0[r] = 0.f; a1[r] = 0.f; }
        for (int k = 0; k < NBITS; k++) {
            float w0 = ix_w1[(NBITS + k) * NH + j0];
            float w1 = ix_w1[(NBITS + k) * NH + j1];
            #pragma unroll
            for (int r = 0; r < ROWS; r++) {
                a0[r] = fmaf(sms[r][k], w0, a0[r]);
                a1[r] = fmaf(sms[r][k], w1, a1[r]);
            }
        }
        #pragma unroll
        for (int r = 0; r < ROWS; r++) {
            g_sp[(b0 + r) * NH + j0] = a0[r];
            g_sp[(b0 + r) * NH + j1] = a1[r];
        }
    }

    {   // v_shift
        const int j = t;
        if (j < NHV) {
            float a[ROWS];
            #pragma unroll
            for (int r = 0; r < ROWS; r++) a[r] = 0.f;
            for (int k = 0; k < NBITS; k++) {
                float w = v_w1[(NBITS + k) * NHV + j];
                #pragma unroll
                for (int r = 0; r < ROWS; r++)
                    a[r] = fmaf(sms[r][k], w, a[r]);
            }
            #pragma unroll
            for (int r = 0; r < ROWS; r++)
                g_vs[(b0 + r) * NHV + j] = a[r];
        }
    }
}

// ---------------------------------------------------------------------------
// Kernel 2: FP8 mma.sync main chain. 512 threads, 4x4 warp grid.
// ---------------------------------------------------------------------------
__global__ __launch_bounds__(512, 1) void main_mma_kernel(
    const float* __restrict__ a_bits,
    const float* __restrict__ ix_w1, const float* __restrict__ ix_b1,
    const float* __restrict__ ix_b2, const float* __restrict__ ix_b3,
    const float* __restrict__ v_w1,  const float* __restrict__ v_b1,
    const float* __restrict__ v_w2,  const float* __restrict__ v_b2,
    float* __restrict__ out)
{
    extern __shared__ char bp[];
    float* b2s  = (float*)(bp + B2_OFF);   // prescaled x16
    float* b3s  = (float*)(bp + B3_OFF);
    float* ab_s = (float*)(bp + AB_OFF);
    float* vs_s = (float*)(bp + VS_OFF);
    float* vw2s = (float*)(bp + VW2_OFF);

    const int t    = threadIdx.x;
    const int lane = t & 31, w = t >> 5;
    const int g = lane >> 2, tg = lane & 3;
    const int mg = w & 3, ng = w >> 2;       // 4x4 warp grid
    const int pair = blockIdx.x;

    const uint32_t smb = smem_u32(bp);

    {   // prologue: W2 chunk 0
        #pragma unroll
        for (int i = 0; i < 2; i++) {
            int idx = t + i * 512;
            int row = idx >> 3, c16 = idx & 7;
            cp16(smb + W2_OFF + row * W2_STR + c16 * 16,
                 g_w2f8 + row * NH + c16 * 16);
        }
        asm volatile("cp.async.commit_group;" ::: "memory");
    }

    for (int i = t; i < NH; i += 512) {
        b2s[i]  = ix_b2[i] * SCALE;
        vs_s[i] = g_vs[(2 * pair + (i >> 8)) * NHV + (i & 255)] + v_b1[i & 255];
    }
    if (t < 256) vw2s[t] = v_w2[t];
    if (t < NBITS) b3s[t] = ix_b3[t];
    if (t < 128)   ab_s[t] = a_bits[(2 * pair + (t >> 6)) * NBITS + (t & 63)];

    // h1 build: e4m3 (x16) [128 rows][512 k], stride 528 B
    #pragma unroll 4
    for (int i = 0; i < 32; i++) {
        int idx = t + i * 512;
        int m = idx >> 7, q = idx & 127;
        int k = q * 4;
        float4 p  = *(const float4*)(ix_w1 + (m & 63) * NH + k);
        float4 s  = *(const float4*)(g_sp + (2 * pair + (m >> 6)) * NH + k);
        float4 bb = *(const float4*)(ix_b1 + k);
        float v0 = fmaxf(p.x + s.x + bb.x, 0.f) * SCALE;
        float v1 = fmaxf(p.y + s.y + bb.y, 0.f) * SCALE;
        float v2 = fmaxf(p.z + s.z + bb.z, 0.f) * SCALE;
        float v3 = fmaxf(p.w + s.w + bb.w, 0.f) * SCALE;
        *(uint32_t*)(bp + H1_OFF + m * H1_STR + k) = pack_e4m3x4(v0, v1, v2, v3);
    }

    float lg[2][2][4];
    #pragma unroll
    for (int mt = 0; mt < 2; mt++)
        #pragma unroll
        for (int nt = 0; nt < 2; nt++)
            #pragma unroll
            for (int j2 = 0; j2 < 4; j2++) lg[mt][nt][j2] = 0.f;

    float acc[2][4][4];

    const uint32_t bfrag = (uint32_t)((lane & 7) * W2_STR + (lane >> 3) * 16);
    uint32_t h1a[2];
    h1a[0] = smb + H1_OFF + (uint32_t)((mg * 32 + (lane & 15)) * H1_STR + (lane >> 4) * 16);
    h1a[1] = h1a[0] + 16 * H1_STR;
    const uint32_t w3b = smb + W3_OFF + (uint32_t)(ng * 16 * W2_STR) + bfrag;

    for (int c = 0; c < 16; c++) {
        const int nb = c >> 2, kb = c & 3;
        const int next = c + 1;
        if (next < 16) {
            int nnb = next >> 2, nkb = next & 3;
            const uint8_t* src = g_w2f8 + (nnb * 128) * NH + nkb * 128;
            uint32_t dstb = smb + W2_OFF + (next & 1) * W2_TILE;
            #pragma unroll
            for (int i = 0; i < 2; i++) {
                int idx = t + i * 512;
                int row = idx >> 3, c16 = idx & 7;
                cp16(dstb + row * W2_STR + c16 * 16, src + row * NH + c16 * 16);
            }
            if (nkb == 1) {   // stage W3 slice for nb=nnb
                int row = t >> 3, c16 = t & 7;
                cp16(smb + W3_OFF + row * W2_STR + c16 * 16,
                     g_w3f8 + row * NH + nnb * 128 + c16 * 16);
            }
            asm volatile("cp.async.commit_group;" ::: "memory");
            asm volatile("cp.async.wait_group 1;" ::: "memory");
        } else {
            asm volatile("cp.async.wait_group 0;" ::: "memory");
        }
        __syncthreads();

        if (kb == 0) {
            #pragma unroll
            for (int mt = 0; mt < 2; mt++)
                #pragma unroll
                for (int nt = 0; nt < 4; nt++) {
                    acc[mt][nt][0] = 0.f; acc[mt][nt][1] = 0.f;
                    acc[mt][nt][2] = 0.f; acc[mt][nt][3] = 0.f;
                }
        }

        const uint32_t bufA = smb + W2_OFF + (c & 1) * W2_TILE;
        const uint32_t w2b = bufA + (uint32_t)(ng * 32 * W2_STR) + bfrag;
        const uint32_t akb = (uint32_t)(kb * 128);   // 128 k-bytes per chunk

        #pragma unroll
        for (int ks2 = 0; ks2 < 2; ks2++) {          // each covers 2 k32 steps
            uint32_t Bv[4][4];
            #pragma unroll
            for (int nt = 0; nt < 4; nt++)
                ldm_x4(Bv[nt], w2b + nt * (8 * W2_STR) + ks2 * 64);
            uint32_t Am[2][2][4];
            #pragma unroll
            for (int mt = 0; mt < 2; mt++) {
                ldm_x4(Am[mt][0], h1a[mt] + akb + (2 * ks2)     * 32);
                ldm_x4(Am[mt][1], h1a[mt] + akb + (2 * ks2 + 1) * 32);
            }
            #pragma unroll
            for (int mt = 0; mt < 2; mt++)
                #pragma unroll
                for (int nt = 0; nt < 4; nt++) {
                    mma_fp8(acc[mt][nt], Am[mt][0], Bv[nt][0], Bv[nt][1]);
                    mma_fp8(acc[mt][nt], Am[mt][1], Bv[nt][2], Bv[nt][3]);
                }
        }

        if (kb == 3) {
            __syncthreads();   // bufA fully read -> reuse for h2 (e4m3 x16)
            #pragma unroll
            for (int mt = 0; mt < 2; mt++)
                #pragma unroll
                for (int nt = 0; nt < 4; nt++) {
                    int col = ng * 32 + nt * 8 + tg * 2;
                    float bb0 = b2s[nb * 128 + col], bb1 = b2s[nb * 128 + col + 1];
                    int r0 = mg * 32 + mt * 16 + g;
                    // h2_scaled = relu(acc/16 + 16*b2)  (acc = 256 x true)
                    uint16_t p0 = pack_e4m3x2(
                        fmaxf(acc[mt][nt][0] * 0.0625f + bb0, 0.f),
                        fmaxf(acc[mt][nt][1] * 0.0625f + bb1, 0.f));
                    uint16_t p1 = pack_e4m3x2(
                        fmaxf(acc[mt][nt][2] * 0.0625f + bb0, 0.f),
                        fmaxf(acc[mt][nt][3] * 0.0625f + bb1, 0.f));
                    *(uint16_t*)(bp + (bufA - smb) + r0 * W2_STR + col) = p0;
                    *(uint16_t*)(bp + (bufA - smb) + (r0 + 8) * W2_STR + col) = p1;
                }
            __syncthreads();

            // GEMM2(nb): rows mg*32 (2 m-tiles) x cols ng*16 (2 n3-tiles)
            uint32_t a2b[2];
            a2b[0] = bufA + (uint32_t)((mg * 32 + (lane & 15)) * W2_STR + (lane >> 4) * 16);
            a2b[1] = a2b[0] + 16 * W2_STR;
            #pragma unroll
            for (int ks2 = 0; ks2 < 2; ks2++) {
                uint32_t B2v[2][4];
                #pragma unroll
                for (int nt = 0; nt < 2; nt++)
                    ldm_x4(B2v[nt], w3b + nt * (8 * W2_STR) + ks2 * 64);
                uint32_t A2[2][2][4];
                #pragma unroll
                for (int mt = 0; mt < 2; mt++) {
                    ldm_x4(A2[mt][0], a2b[mt] + (2 * ks2)     * 32);
                    ldm_x4(A2[mt][1], a2b[mt] + (2 * ks2 + 1) * 32);
                }
                #pragma unroll
                for (int mt = 0; mt < 2; mt++)
                    #pragma unroll
                    for (int nt = 0; nt < 2; nt++) {
                        mma_fp8(lg[mt][nt], A2[mt][0], B2v[nt][0], B2v[nt][1]);
                        mma_fp8(lg[mt][nt], A2[mt][1], B2v[nt][2], B2v[nt][3]);
                    }
            }
        }
        __syncthreads();
    }

    // logits -> smem (f32, stride 68), reusing W2 buffer 0
    float* lbuf = (float*)(bp + LG_OFF);
    #pragma unroll
    for (int mt = 0; mt < 2; mt++)
        #pragma unroll
        for (int nt = 0; nt < 2; nt++) {
            int col = ng * 16 + nt * 8 + tg * 2;
            int r0 = mg * 32 + mt * 16 + g;
            lbuf[r0 * 68 + col]     = lg[mt][nt][0];
            lbuf[r0 * 68 + col + 1] = lg[mt][nt][1];
            lbuf[(r0 + 8) * 68 + col]     = lg[mt][nt][2];
            lbuf[(r0 + 8) * 68 + col + 1] = lg[mt][nt][3];
        }
    __syncthreads();

    // epilogue: 4 threads per row (quad), 128 rows. lg = 256 x true logits.
    {
        const int row = t >> 2, tq = t & 3;
        const int bsel = row >> 6, R = row & 63;
        float v[16];
        float mx = -1e30f;
        #pragma unroll
        for (int i = 0; i < 16; i++) {
            int col = i * 4 + tq;
            v[i] = lbuf[row * 68 + col] * INV_SC2 + b3s[col];
            mx = fmaxf(mx, v[i]);
        }
        mx = fmaxf(mx, __shfl_xor_sync(0xffffffffu, mx, 1));
        mx = fmaxf(mx, __shfl_xor_sync(0xffffffffu, mx, 2));

        const float* abr = ab_s + bsel * NBITS;
        float den = 0.f, num = 0.f;
        #pragma unroll
        for (int i = 0; i < 16; i++) {
            float e = expf(v[i] - mx);
            den += e;
            num = fmaf(e, abr[i * 4 + tq], num);
        }
        den += __shfl_xor_sync(0xffffffffu, den, 1);
        den += __shfl_xor_sync(0xffffffffu, den, 2);
        num += __shfl_xor_sync(0xffffffffu, num, 1);
        num += __shfl_xor_sync(0xffffffffu, num, 2);
        float pointed = num / den;

        const float* vrow = v_w1 + R * NHV;
        const float* vsr  = vs_s + bsel * NHV;
        float acc2 = 0.f;
        #pragma unroll 8
        for (int jj = 0; jj < 64; jj++) {
            int j = jj * 4 + tq;
            float vh = fmaxf(vrow[j] + vsr[j], 0.f);
            acc2 = fmaf(vh, vw2s[j], acc2);
        }
        acc2 += __shfl_xor_sync(0xffffffffu, acc2, 1);
        acc2 += __shfl_xor_sync(0xffffffffu, acc2, 2);
        if (tq == 0) {
            float vlog = acc2 + v_b2[0];
            out[(2 * pair + bsel) * NBITS + R] =
                pointed * (1.f / (1.f + expf(-vlog)));
        }
    }
}

extern "C" void kernel_launch(void* const* d_in, const int* in_sizes, int n_in,
                              void* d_out, int out_size)
{
    const float* a_bits     = (const float*)d_in[0];
    const float* shift_bits = (const float*)d_in[1];
    const float* sd_w1 = (const float*)d_in[2];
    const float* sd_b1 = (const float*)d_in[3];
    const float* sd_w2 = (const float*)d_in[4];
    const float* sd_b2 = (const float*)d_in[5];
    const float* sd_w3 = (const float*)d_in[6];
    const float* sd_b3 = (const float*)d_in[7];
    const float* ix_w1 = (const float*)d_in[8];
    const float* ix_b1 = (const float*)d_in[9];
    const float* ix_w2 = (const float*)d_in[10];
    const float* ix_b2 = (const float*)d_in[11];
    const float* ix_w3 = (const float*)d_in[12];
    const float* ix_b3 = (const float*)d_in[13];
    const float* v_w1  = (const float*)d_in[14];
    const float* v_b1  = (const float*)d_in[15];
    const float* v_w2  = (const float*)d_in[16];
    const float* v_b2  = (const float*)d_in[17];
    float* out = (float*)d_out;

    cudaFuncSetAttribute(main_mma_kernel,
                         cudaFuncAttributeMaxDynamicSharedMemorySize, SM_TOTAL);

    aux_kernel<<<800, 256>>>(shift_bits, sd_w1, sd_b1, sd_w2, sd_b2,
                             sd_w3, sd_b3, ix_w1, v_w1, ix_w2, ix_w3);
    main_mma_kernel<<<NB / 2, 512, SM_TOTAL>>>(a_bits, ix_w1, ix_b1, ix_b2, ix_b3,
                                               v_w1, v_b1, v_w2, v_b2, out);
}

// round 12
// speedup vs baseline: 1.0777x; 1.0777x over previous
#include <cuda_runtime.h>
#include <cuda_bf16.h>
#include <math.h>
#include <stdint.h>

#define NB    2048
#define NBITS 64
#define NH    512
#define NHV   256

__device__ float g_sp[NB * NH];
__device__ float g_vs[NB * NHV];
__device__ uint8_t g_w2f8[NH * NH];     // W2^T e4m3 (x16)  [n][k]
__device__ uint8_t g_w3f8[NBITS * NH];  // W3^T e4m3 (x16)  [n3][k]

__device__ __forceinline__ uint32_t smem_u32(const void* p) {
    uint32_t a;
    asm("{ .reg .u64 t; cvta.to.shared.u64 t, %1; cvt.u32.u64 %0, t; }"
        : "=r"(a) : "l"(p));
    return a;
}
__device__ __forceinline__ uint16_t pack_e4m3x2(float lo, float hi) {
    uint16_t r;
    asm("cvt.rn.satfinite.e4m3x2.f32 %0, %1, %2;" : "=h"(r) : "f"(hi), "f"(lo));
    return r;
}
__device__ __forceinline__ uint32_t pack_e4m3x4(float a, float b, float c, float d) {
    uint16_t lo = pack_e4m3x2(a, b);
    uint16_t hi = pack_e4m3x2(c, d);
    uint32_t r;
    asm("mov.b32 %0, {%1, %2};" : "=r"(r) : "h"(lo), "h"(hi));
    return r;
}
__device__ __forceinline__ void cp16(uint32_t dst, const void* src) {
    asm volatile("cp.async.cg.shared.global [%0], [%1], 16;"
                 :: "r"(dst), "l"(src) : "memory");
}
__device__ __forceinline__ void mma_fp8(float* c, const uint32_t* a,
                                        uint32_t b0, uint32_t b1) {
    asm volatile("mma.sync.aligned.m16n8k32.row.col.f32.e4m3.e4m3.f32 "
                 "{%0,%1,%2,%3}, {%4,%5,%6,%7}, {%8,%9}, {%0,%1,%2,%3};"
                 : "+f"(c[0]), "+f"(c[1]), "+f"(c[2]), "+f"(c[3])
                 : "r"(a[0]), "r"(a[1]), "r"(a[2]), "r"(a[3]),
                   "r"(b0), "r"(b1));
}
__device__ __forceinline__ void ldm_x4(uint32_t* r, uint32_t addr) {
    asm volatile("ldmatrix.sync.aligned.m8n8.x4.shared.b16 {%0,%1,%2,%3}, [%4];"
                 : "=r"(r[0]), "=r"(r[1]), "=r"(r[2]), "=r"(r[3]) : "r"(addr));
}

#define SCALE     16.0f
#define INV_SC2   (1.0f / 256.0f)

// SMEM layout (fp8, M=64 per CTA): total 84480 B -> 2 CTAs/SM
#define H1_OFF   0         // 64 rows x 528 = 33792
#define H1_STR   528
#define W2_OFF   33792     // 2 x 18432
#define W2_TILE  18432
#define W2_STR   144
#define W3_OFF   70656     // 64 x 144 = 9216
#define B2_OFF   79872     // 512 f32 (prescaled x16) = 2048
#define B3_OFF   81920     // 64 f32
#define AB_OFF   82176     // 64 f32
#define VS_OFF   82432     // 256 f32
#define VW2_OFF  83456     // 256 f32
#define SM_TOTAL 84480
#define LG_OFF   W2_OFF    // logits f32 (64 x 68 x 4 = 17408 <= 18432)

// ---------------------------------------------------------------------------
// Fused aux: shift MLP (blocks 0..511) + W2 fp8 prep (512..767) + W3 (768..799)
// ---------------------------------------------------------------------------
__global__ __launch_bounds__(256) void aux_kernel(
    const float* __restrict__ shift_bits,
    const float* __restrict__ sd_w1, const float* __restrict__ sd_b1,
    const float* __restrict__ sd_w2, const float* __restrict__ sd_b2,
    const float* __restrict__ sd_w3, const float* __restrict__ sd_b3,
    const float* __restrict__ ix_w1, const float* __restrict__ v_w1,
    const float* __restrict__ ix_w2, const float* __restrict__ ix_w3)
{
    const int bid = blockIdx.x;
    const int t   = threadIdx.x;

    if (bid >= 512) {
        if (bid < 768) {                       // W2: transpose + scale + fp8
            int idx = (bid - 512) * 256 + t;
            int n = idx >> 7, k4 = (idx & 127) * 4;
            float w0 = ix_w2[(k4 + 0) * NH + n] * SCALE;
            float w1 = ix_w2[(k4 + 1) * NH + n] * SCALE;
            float w2v = ix_w2[(k4 + 2) * NH + n] * SCALE;
            float w3v = ix_w2[(k4 + 3) * NH + n] * SCALE;
            ((uint32_t*)g_w2f8)[n * 128 + (idx & 127)] = pack_e4m3x4(w0, w1, w2v, w3v);
        } else {                               // W3
            int idx = (bid - 768) * 256 + t;
            int n3 = idx >> 7, k4g = idx & 127;
            int k4 = k4g * 4;
            float w0 = ix_w3[(k4 + 0) * NBITS + n3] * SCALE;
            float w1 = ix_w3[(k4 + 1) * NBITS + n3] * SCALE;
            float w2v = ix_w3[(k4 + 2) * NBITS + n3] * SCALE;
            float w3v = ix_w3[(k4 + 3) * NBITS + n3] * SCALE;
            ((uint32_t*)g_w3f8)[n3 * 128 + k4g] = pack_e4m3x4(w0, w1, w2v, w3v);
        }
        return;
    }

    // ---- shift MLP, 4 batch rows per block ----
    const int ROWS = 4;
    __shared__ float xs[ROWS][NBITS];
    __shared__ float hs[ROWS][NH];
    __shared__ float gs[ROWS][NH];
    __shared__ float lgs[ROWS][NBITS];
    __shared__ float sms[ROWS][NBITS];

    const int b0 = bid * ROWS;

    for (int idx = t; idx < ROWS * NBITS; idx += 256) {
        int r = idx >> 6, k = idx & 63;
        xs[r][k] = shift_bits[(b0 + r) * NBITS + k];
    }
    __syncthreads();

    {   // layer 1
        const int j0 = t, j1 = t + 256;
        float a0[ROWS], a1[ROWS];
        #pragma unroll
        for (int r = 0; r < ROWS; r++) { a0[r] = 0.f; a1[r] = 0.f; }
        for (int k = 0; k < NBITS; k++) {
            float w0 = sd_w1[k * NH + j0];
            float w1 = sd_w1[k * NH + j1];
            #pragma unroll
            for (int r = 0; r < ROWS; r++) {
                a0[r] = fmaf(xs[r][k], w0, a0[r]);
                a1[r] = fmaf(xs[r][k], w1, a1[r]);
            }
        }
        float bb0 = sd_b1[j0], bb1 = sd_b1[j1];
        #pragma unroll
        for (int r = 0; r < ROWS; r++) {
            hs[r][j0] = fmaxf(a0[r] + bb0, 0.f);
            hs[r][j1] = fmaxf(a1[r] + bb1, 0.f);
        }
    }
    __syncthreads();

    {   // layer 2
        const int j0 = t, j1 = t + 256;
        float a0[ROWS], a1[ROWS];
        #pragma unroll
        for (int r = 0; r < ROWS; r++) { a0[r] = 0.f; a1[r] = 0.f; }
        for (int k = 0; k < NH; k++) {
            float w0 = sd_w2[k * NH + j0];
            float w1 = sd_w2[k * NH + j1];
            #pragma unroll
            for (int r = 0; r < ROWS; r++) {
                a0[r] = fmaf(hs[r][k], w0, a0[r]);
                a1[r] = fmaf(hs[r][k], w1, a1[r]);
            }
        }
        float bb0 = sd_b2[j0], bb1 = sd_b2[j1];
        #pragma unroll
        for (int r = 0; r < ROWS; r++) {
            gs[r][j0] = fmaxf(a0[r] + bb0, 0.f);
            gs[r][j1] = fmaxf(a1[r] + bb1, 0.f);
        }
    }
    __syncthreads();

    {   // layer 3
        int r = t >> 6, j = t & 63;
        float acc = 0.f;
        for (int k = 0; k < NH; k++)
            acc = fmaf(gs[r][k], sd_w3[k * NBITS + j], acc);
        lgs[r][j] = acc + sd_b3[j];
    }
    __syncthreads();

    {   // softmax over 64 (warps 0..3 -> rows)
        int wr = t >> 5, l = t & 31;
        if (wr < ROWS) {
            float v0 = lgs[wr][l], v1 = lgs[wr][l + 32];
            float m = fmaxf(v0, v1);
            #pragma unroll
            for (int o = 16; o > 0; o >>= 1) m = fmaxf(m, __shfl_xor_sync(0xffffffffu, m, o));
            float e0 = expf(v0 - m), e1 = expf(v1 - m);
            float s = e0 + e1;
            #pragma unroll
            for (int o = 16; o > 0; o >>= 1) s += __shfl_xor_sync(0xffffffffu, s, o);
            float inv = 1.f / s;
            sms[wr][l] = e0 * inv;
            sms[wr][l + 32] = e1 * inv;
        }
    }
    __syncthreads();

    {   // shift_part
        const int j0 = t, j1 = t + 256;
        float a0[ROWS], a1[ROWS];
        #pragma unroll
        for (int r = 0; r < ROWS; r++) { a0[r] = 0.f; a1[r] = 0.f; }
        for (int k = 0; k < NBITS; k++) {
            float w0 = ix_w1[(NBITS + k) * NH + j0];
            float w1 = ix_w1[(NBITS + k) * NH + j1];
            #pragma unroll
            for (int r = 0; r < ROWS; r++) {
                a0[r] = fmaf(sms[r][k], w0, a0[r]);
                a1[r] = fmaf(sms[r][k], w1, a1[r]);
            }
        }
        #pragma unroll
        for (int r = 0; r < ROWS; r++) {
            g_sp[(b0 + r) * NH + j0] = a0[r];
            g_sp[(b0 + r) * NH + j1] = a1[r];
        }
    }

    {   // v_shift
        const int j = t;
        if (j < NHV) {
            float a[ROWS];
            #pragma unroll
            for (int r = 0; r < ROWS; r++) a[r] = 0.f;
            for (int k = 0; k < NBITS; k++) {
                float w = v_w1[(NBITS + k) * NHV + j];
                #pragma unroll
                for (int r = 0; r < ROWS; r++)
                    a[r] = fmaf(sms[r][k], w, a[r]);
            }
            #pragma unroll
            for (int r = 0; r < ROWS; r++)
                g_vs[(b0 + r) * NHV + j] = a[r];
        }
    }
}

// ---------------------------------------------------------------------------
// Kernel 2: FP8 mma.sync, M=64 (1 batch/CTA), 256 threads, 2 CTAs/SM.
// Warp grid 2m x 4n; GEMM1 warp tile 32m x 32n; GEMM2 32m x 16n3.
// ---------------------------------------------------------------------------
__global__ __launch_bounds__(256, 2) void main_mma_kernel(
    const float* __restrict__ a_bits,
    const float* __restrict__ ix_w1, const float* __restrict__ ix_b1,
    const float* __restrict__ ix_b2, const float* __restrict__ ix_b3,
    const float* __restrict__ v_w1,  const float* __restrict__ v_b1,
    const float* __restrict__ v_w2,  const float* __restrict__ v_b2,
    float* __restrict__ out)
{
    extern __shared__ char bp[];
    float* b2s  = (float*)(bp + B2_OFF);   // prescaled x16
    float* b3s  = (float*)(bp + B3_OFF);
    float* ab_s = (float*)(bp + AB_OFF);
    float* vs_s = (float*)(bp + VS_OFF);
    float* vw2s = (float*)(bp + VW2_OFF);

    const int t    = threadIdx.x;
    const int lane = t & 31, w = t >> 5;     // 8 warps
    const int g = lane >> 2, tg = lane & 3;
    const int mg = w & 1, ng = w >> 1;       // 2m x 4n warp grid
    const int b  = blockIdx.x;               // one batch per CTA

    const uint32_t smb = smem_u32(bp);

    {   // prologue: W2 chunk 0 (1024 cp16)
        #pragma unroll
        for (int i = 0; i < 4; i++) {
            int idx = t + i * 256;
            int row = idx >> 3, c16 = idx & 7;
            cp16(smb + W2_OFF + row * W2_STR + c16 * 16,
                 g_w2f8 + row * NH + c16 * 16);
        }
        asm volatile("cp.async.commit_group;" ::: "memory");
    }

    for (int i = t; i < NH; i += 256)
        b2s[i] = ix_b2[i] * SCALE;
    vs_s[t] = (t < NHV) ? (g_vs[b * NHV + t] + v_b1[t]) : 0.f;
    if (t >= NHV) vw2s[t - NHV] = v_w2[t - NHV];
    else if (t < NHV) vw2s[t] = v_w2[t];     // both halves covered; benign dup
    if (t < NBITS) { b3s[t] = ix_b3[t]; ab_s[t] = a_bits[b * NBITS + t]; }

    // h1 build: e4m3 (x16) [64 rows][512 k], stride 528 B
    #pragma unroll 4
    for (int i = 0; i < 16; i++) {
        int idx = t + i * 256;               // 0..4095 (uint32 units)
        int m = idx >> 6, q = idx & 63;      // hmm: 64 rows x 128 u32 per row
        // recompute: per row 512 e4m3 = 128 u32 -> idx: m = idx>>7, q = idx&127
        (void)m; (void)q;
        int mm = idx >> 7, qq = idx & 127;
        int k = qq * 4;
        float4 p  = *(const float4*)(ix_w1 + mm * NH + k);
        float4 s  = *(const float4*)(g_sp + b * NH + k);
        float4 bb = *(const float4*)(ix_b1 + k);
        float v0 = fmaxf(p.x + s.x + bb.x, 0.f) * SCALE;
        float v1 = fmaxf(p.y + s.y + bb.y, 0.f) * SCALE;
        float v2 = fmaxf(p.z + s.z + bb.z, 0.f) * SCALE;
        float v3 = fmaxf(p.w + s.w + bb.w, 0.f) * SCALE;
        *(uint32_t*)(bp + H1_OFF + mm * H1_STR + k) = pack_e4m3x4(v0, v1, v2, v3);
    }
    // 64 rows x 128 u32 = 8192 u32; 256 thr x 32 iters -> loop count is 32
    #pragma unroll 4
    for (int i = 16; i < 32; i++) {
        int idx = t + i * 256;
        int mm = idx >> 7, qq = idx & 127;
        int k = qq * 4;
        float4 p  = *(const float4*)(ix_w1 + mm * NH + k);
        float4 s  = *(const float4*)(g_sp + b * NH + k);
        float4 bb = *(const float4*)(ix_b1 + k);
        float v0 = fmaxf(p.x + s.x + bb.x, 0.f) * SCALE;
        float v1 = fmaxf(p.y + s.y + bb.y, 0.f) * SCALE;
        float v2 = fmaxf(p.z + s.z + bb.z, 0.f) * SCALE;
        float v3 = fmaxf(p.w + s.w + bb.w, 0.f) * SCALE;
        *(uint32_t*)(bp + H1_OFF + mm * H1_STR + k) = pack_e4m3x4(v0, v1, v2, v3);
    }

    float lg[2][2][4];    // GEMM2: rows mg*32+mt*16, cols ng*16+nt*8
    #pragma unroll
    for (int mt = 0; mt < 2; mt++)
        #pragma unroll
        for (int nt = 0; nt < 2; nt++)
            #pragma unroll
            for (int j2 = 0; j2 < 4; j2++) lg[mt][nt][j2] = 0.f;

    float acc[2][4][4];   // GEMM1: rows mg*32+mt*16, cols ng*32+nt*8

    const uint32_t bfrag = (uint32_t)((lane & 7) * W2_STR + (lane >> 3) * 16);
    uint32_t h1a[2];
    h1a[0] = smb + H1_OFF + (uint32_t)((mg * 32 + (lane & 15)) * H1_STR + (lane >> 4) * 16);
    h1a[1] = h1a[0] + 16 * H1_STR;
    const uint32_t w3b = smb + W3_OFF + (uint32_t)(ng * 16 * W2_STR) + bfrag;

    for (int c = 0; c < 16; c++) {
        const int nb = c >> 2, kb = c & 3;
        const int next = c + 1;
        if (next < 16) {
            int nnb = next >> 2, nkb = next & 3;
            const uint8_t* src = g_w2f8 + (nnb * 128) * NH + nkb * 128;
            uint32_t dstb = smb + W2_OFF + (next & 1) * W2_TILE;
            #pragma unroll
            for (int i = 0; i < 4; i++) {
                int idx = t + i * 256;
                int row = idx >> 3, c16 = idx & 7;
                cp16(dstb + row * W2_STR + c16 * 16, src + row * NH + c16 * 16);
            }
            if (nkb == 1) {   // stage W3 slice for nb=nnb (512 cp16)
                #pragma unroll
                for (int i = 0; i < 2; i++) {
                    int idx = t + i * 256;
                    int row = idx >> 3, c16 = idx & 7;
                    cp16(smb + W3_OFF + row * W2_STR + c16 * 16,
                         g_w3f8 + row * NH + nnb * 128 + c16 * 16);
                }
            }
            asm volatile("cp.async.commit_group;" ::: "memory");
            asm volatile("cp.async.wait_group 1;" ::: "memory");
        } else {
            asm volatile("cp.async.wait_group 0;" ::: "memory");
        }
        __syncthreads();

        if (kb == 0) {
            #pragma unroll
            for (int mt = 0; mt < 2; mt++)
                #pragma unroll
                for (int nt = 0; nt < 4; nt++) {
                    acc[mt][nt][0] = 0.f; acc[mt][nt][1] = 0.f;
                    acc[mt][nt][2] = 0.f; acc[mt][nt][3] = 0.f;
                }
        }

        const uint32_t bufA = smb + W2_OFF + (c & 1) * W2_TILE;
        const uint32_t w2b = bufA + (uint32_t)(ng * 32 * W2_STR) + bfrag;
        const uint32_t akb = (uint32_t)(kb * 128);

        #pragma unroll
        for (int ks2 = 0; ks2 < 2; ks2++) {
            uint32_t Bv[4][4];
            #pragma unroll
            for (int nt = 0; nt < 4; nt++)
                ldm_x4(Bv[nt], w2b + nt * (8 * W2_STR) + ks2 * 64);
            uint32_t Am[2][2][4];
            #pragma unroll
            for (int mt = 0; mt < 2; mt++) {
                ldm_x4(Am[mt][0], h1a[mt] + akb + (2 * ks2)     * 32);
                ldm_x4(Am[mt][1], h1a[mt] + akb + (2 * ks2 + 1) * 32);
            }
            #pragma unroll
            for (int mt = 0; mt < 2; mt++)
                #pragma unroll
                for (int nt = 0; nt < 4; nt++) {
                    mma_fp8(acc[mt][nt], Am[mt][0], Bv[nt][0], Bv[nt][1]);
                    mma_fp8(acc[mt][nt], Am[mt][1], Bv[nt][2], Bv[nt][3]);
                }
        }

        if (kb == 3) {
            __syncthreads();   // bufA fully read -> reuse for h2 (e4m3 x16)
            #pragma unroll
            for (int mt = 0; mt < 2; mt++)
                #pragma unroll
                for (int nt = 0; nt < 4; nt++) {
                    int col = ng * 32 + nt * 8 + tg * 2;
                    float bb0 = b2s[nb * 128 + col], bb1 = b2s[nb * 128 + col + 1];
                    int r0 = mg * 32 + mt * 16 + g;
                    uint16_t p0 = pack_e4m3x2(
                        fmaxf(acc[mt][nt][0] * 0.0625f + bb0, 0.f),
                        fmaxf(acc[mt][nt][1] * 0.0625f + bb1, 0.f));
                    uint16_t p1 = pack_e4m3x2(
                        fmaxf(acc[mt][nt][2] * 0.0625f + bb0, 0.f),
                        fmaxf(acc[mt][nt][3] * 0.0625f + bb1, 0.f));
                    *(uint16_t*)(bp + (bufA - smb) + r0 * W2_STR + col) = p0;
                    *(uint16_t*)(bp + (bufA - smb) + (r0 + 8) * W2_STR + col) = p1;
                }
            __syncthreads();

            // GEMM2(nb): rows mg*32 (2 m-tiles) x cols ng*16 (2 n3-tiles)
            uint32_t a2b[2];
            a2b[0] = bufA + (uint32_t)((mg * 32 + (lane & 15)) * W2_STR + (lane >> 4) * 16);
            a2b[1] = a2b[0] + 16 * W2_STR;
            #pragma unroll
            for (int ks2 = 0; ks2 < 2; ks2++) {
                uint32_t B2v[2][4];
                #pragma unroll
                for (int nt = 0; nt < 2; nt++)
                    ldm_x4(B2v[nt], w3b + nt * (8 * W2_STR) + ks2 * 64);
                uint32_t A2[2][2][4];
                #pragma unroll
                for (int mt = 0; mt < 2; mt++) {
                    ldm_x4(A2[mt][0], a2b[mt] + (2 * ks2)     * 32);
                    ldm_x4(A2[mt][1], a2b[mt] + (2 * ks2 + 1) * 32);
                }
                #pragma unroll
                for (int mt = 0; mt < 2; mt++)
                    #pragma unroll
                    for (int nt = 0; nt < 2; nt++) {
                        mma_fp8(lg[mt][nt], A2[mt][0], B2v[nt][0], B2v[nt][1]);
                        mma_fp8(lg[mt][nt], A2[mt][1], B2v[nt][2], B2v[nt][3]);
                    }
            }
        }
        __syncthreads();
    }

    // logits -> smem (f32, stride 68), reusing W2 buffer 0
    float* lbuf = (float*)(bp + LG_OFF);
    #pragma unroll
    for (int mt = 0; mt < 2; mt++)
        #pragma unroll
        for (int nt = 0; nt < 2; nt++) {
            int col = ng * 16 + nt * 8 + tg * 2;
            int r0 = mg * 32 + mt * 16 + g;
            lbuf[r0 * 68 + col]     = lg[mt][nt][0];
            lbuf[r0 * 68 + col + 1] = lg[mt][nt][1];
            lbuf[(r0 + 8) * 68 + col]     = lg[mt][nt][2];
            lbuf[(r0 + 8) * 68 + col + 1] = lg[mt][nt][3];
        }
    __syncthreads();

    // epilogue: 4 threads per row (quad), 64 rows. lg = 256 x true logits.
    {
        const int row = t >> 2, tq = t & 3;   // row 0..63
        float v[16];
        float mx = -1e30f;
        #pragma unroll
        for (int i = 0; i < 16; i++) {
            int col = i * 4 + tq;
            v[i] = lbuf[row * 68 + col] * INV_SC2 + b3s[col];
            mx = fmaxf(mx, v[i]);
        }
        mx = fmaxf(mx, __shfl_xor_sync(0xffffffffu, mx, 1));
        mx = fmaxf(mx, __shfl_xor_sync(0xffffffffu, mx, 2));

        float den = 0.f, num = 0.f;
        #pragma unroll
        for (int i = 0; i < 16; i++) {
            float e = expf(v[i] - mx);
            den += e;
            num = fmaf(e, ab_s[i * 4 + tq], num);
        }
        den += __shfl_xor_sync(0xffffffffu, den, 1);
        den += __shfl_xor_sync(0xffffffffu, den, 2);
        num += __shfl_xor_sync(0xffffffffu, num, 1);
        num += __shfl_xor_sync(0xffffffffu, num, 2);
        float pointed = num / den;

        const float* vrow = v_w1 + row * NHV;
        float acc2 = 0.f;
        #pragma unroll 8
        for (int jj = 0; jj < 64; jj++) {
            int j = jj * 4 + tq;
            float vh = fmaxf(vrow[j] + vs_s[j], 0.f);
            acc2 = fmaf(vh, vw2s[j], acc2);
        }
        acc2 += __shfl_xor_sync(0xffffffffu, acc2, 1);
        acc2 += __shfl_xor_sync(0xffffffffu, acc2, 2);
        if (tq == 0) {
            float vlog = acc2 + v_b2[0];
            out[b * NBITS + row] = pointed * (1.f / (1.f + expf(-vlog)));
        }
    }
}

extern "C" void kernel_launch(void* const* d_in, const int* in_sizes, int n_in,
                              void* d_out, int out_size)
{
    const float* a_bits     = (const float*)d_in[0];
    const float* shift_bits = (const float*)d_in[1];
    const float* sd_w1 = (const float*)d_in[2];
    const float* sd_b1 = (const float*)d_in[3];
    const float* sd_w2 = (const float*)d_in[4];
    const float* sd_b2 = (const float*)d_in[5];
    const float* sd_w3 = (const float*)d_in[6];
    const float* sd_b3 = (const float*)d_in[7];
    const float* ix_w1 = (const float*)d_in[8];
    const float* ix_b1 = (const float*)d_in[9];
    const float* ix_w2 = (const float*)d_in[10];
    const float* ix_b2 = (const float*)d_in[11];
    const float* ix_w3 = (const float*)d_in[12];
    const float* ix_b3 = (const float*)d_in[13];
    const float* v_w1  = (const float*)d_in[14];
    const float* v_b1  = (const float*)d_in[15];
    const float* v_w2  = (const float*)d_in[16];
    const float* v_b2  = (const float*)d_in[17];
    float* out = (float*)d_out;

    cudaFuncSetAttribute(main_mma_kernel,
                         cudaFuncAttributeMaxDynamicSharedMemorySize, SM_TOTAL);

    aux_kernel<<<800, 256>>>(shift_bits, sd_w1, sd_b1, sd_w2, sd_b2,
                             sd_w3, sd_b3, ix_w1, v_w1, ix_w2, ix_w3);
    main_mma_kernel<<<NB, 256, SM_TOTAL>>>(a_bits, ix_w1, ix_b1, ix_b2, ix_b3,
                                           v_w1, v_b1, v_w2, v_b2, out);
}

// round 13
// speedup vs baseline: 1.1656x; 1.0816x over previous
#include <cuda_runtime.h>
#include <cuda_bf16.h>
#include <math.h>
#include <stdint.h>

#define NB    2048
#define NBITS 64
#define NH    512
#define NHV   256

typedef unsigned long long ull;

__device__ float g_sp[NB * NH];
__device__ float g_vs[NB * NHV];
__device__ uint8_t g_w2f8[NH * NH];     // W2^T e4m3 (x16)  [n][k]
__device__ uint8_t g_w3f8[NBITS * NH];  // W3^T e4m3 (x16)  [n3][k]

__device__ __forceinline__ uint32_t smem_u32(const void* p) {
    uint32_t a;
    asm("{ .reg .u64 t; cvta.to.shared.u64 t, %1; cvt.u32.u64 %0, t; }"
        : "=r"(a) : "l"(p));
    return a;
}
__device__ __forceinline__ uint16_t pack_e4m3x2(float lo, float hi) {
    uint16_t r;
    asm("cvt.rn.satfinite.e4m3x2.f32 %0, %1, %2;" : "=h"(r) : "f"(hi), "f"(lo));
    return r;
}
__device__ __forceinline__ uint32_t pack_e4m3x4(float a, float b, float c, float d) {
    uint16_t lo = pack_e4m3x2(a, b);
    uint16_t hi = pack_e4m3x2(c, d);
    uint32_t r;
    asm("mov.b32 %0, {%1, %2};" : "=r"(r) : "h"(lo), "h"(hi));
    return r;
}
__device__ __forceinline__ void cp16(uint32_t dst, const void* src) {
    asm volatile("cp.async.cg.shared.global [%0], [%1], 16;"
                 :: "r"(dst), "l"(src) : "memory");
}
__device__ __forceinline__ void mma_fp8(float* c, const uint32_t* a,
                                        uint32_t b0, uint32_t b1) {
    asm volatile("mma.sync.aligned.m16n8k32.row.col.f32.e4m3.e4m3.f32 "
                 "{%0,%1,%2,%3}, {%4,%5,%6,%7}, {%8,%9}, {%0,%1,%2,%3};"
                 : "+f"(c[0]), "+f"(c[1]), "+f"(c[2]), "+f"(c[3])
                 : "r"(a[0]), "r"(a[1]), "r"(a[2]), "r"(a[3]),
                   "r"(b0), "r"(b1));
}
__device__ __forceinline__ void ldm_x4(uint32_t* r, uint32_t addr) {
    asm volatile("ldmatrix.sync.aligned.m8n8.x4.shared.b16 {%0,%1,%2,%3}, [%4];"
                 : "=r"(r[0]), "=r"(r[1]), "=r"(r[2]), "=r"(r[3]) : "r"(addr));
}
// packed f32x2 helpers (aux kernel)
__device__ __forceinline__ void ffma2(ull& c, ull a, ull b) {
    asm("fma.rn.f32x2 %0, %1, %2, %0;" : "+l"(c) : "l"(a), "l"(b));
}
__device__ __forceinline__ ull dupf(float x) {
    ull r; asm("mov.b64 %0, {%1, %1};" : "=l"(r) : "f"(x)); return r;
}
__device__ __forceinline__ ull packf2(float x, float y) {
    ull r; asm("mov.b64 %0, {%1, %2};" : "=l"(r) : "f"(x), "f"(y)); return r;
}
__device__ __forceinline__ float2 unpf2(ull v) {
    float2 r; asm("mov.b64 {%0, %1}, %2;" : "=f"(r.x), "=f"(r.y) : "l"(v)); return r;
}

#define SCALE     16.0f
#define INV_SC2   (1.0f / 256.0f)

// SMEM layout (fp8, M=64 per CTA): total 84480 B -> 2 CTAs/SM
#define H1_OFF   0
#define H1_STR   528
#define W2_OFF   33792
#define W2_TILE  18432
#define W2_STR   144
#define W3_OFF   70656
#define B2_OFF   79872
#define B3_OFF   81920
#define AB_OFF   82176
#define VS_OFF   82432
#define VW2_OFF  83456
#define SM_TOTAL 84480
#define LG_OFF   W2_OFF

// ---------------------------------------------------------------------------
// Fused aux: shift MLP w/ FFMA2 row-pair packing (blocks 0..255, 8 rows each)
// + W2 fp8 prep (256..511) + W3 fp8 prep (512..543).
// f32x2 lanes = batch rows {p, p+4}; weight col pairs via LDG.64.
// Per-row accumulation k-order identical to scalar version -> bit-identical.
// ---------------------------------------------------------------------------
__global__ __launch_bounds__(256) void aux_kernel(
    const float* __restrict__ shift_bits,
    const float* __restrict__ sd_w1, const float* __restrict__ sd_b1,
    const float* __restrict__ sd_w2, const float* __restrict__ sd_b2,
    const float* __restrict__ sd_w3, const float* __restrict__ sd_b3,
    const float* __restrict__ ix_w1, const float* __restrict__ v_w1,
    const float* __restrict__ ix_w2, const float* __restrict__ ix_w3)
{
    const int bid = blockIdx.x;
    const int t   = threadIdx.x;

    if (bid >= 256) {
        if (bid < 512) {                       // W2: transpose + scale + fp8
            int idx = (bid - 256) * 256 + t;   // 0..65535
            int n = idx >> 7, k4 = (idx & 127) * 4;
            float w0 = ix_w2[(k4 + 0) * NH + n] * SCALE;
            float w1 = ix_w2[(k4 + 1) * NH + n] * SCALE;
            float w2v = ix_w2[(k4 + 2) * NH + n] * SCALE;
            float w3v = ix_w2[(k4 + 3) * NH + n] * SCALE;
            ((uint32_t*)g_w2f8)[n * 128 + (idx & 127)] = pack_e4m3x4(w0, w1, w2v, w3v);
        } else {                               // W3
            int idx = (bid - 512) * 256 + t;   // 0..8191
            int n3 = idx >> 7, k4g = idx & 127;
            int k4 = k4g * 4;
            float w0 = ix_w3[(k4 + 0) * NBITS + n3] * SCALE;
            float w1 = ix_w3[(k4 + 1) * NBITS + n3] * SCALE;
            float w2v = ix_w3[(k4 + 2) * NBITS + n3] * SCALE;
            float w3v = ix_w3[(k4 + 3) * NBITS + n3] * SCALE;
            ((uint32_t*)g_w3f8)[n3 * 128 + k4g] = pack_e4m3x4(w0, w1, w2v, w3v);
        }
        return;
    }

    // ---- shift MLP, 8 batch rows per block, row-pair f32x2 ----
    __shared__ ull  xs2[4][NBITS];    // {row p, row p+4}
    __shared__ ull  hs2[4][NH];
    __shared__ ull  gs2[4][NH];
    __shared__ float lgs[8][NBITS];
    __shared__ float sms[8][NBITS];
    __shared__ ull  sms2[4][NBITS];

    const int b0 = bid * 8;
    const int c0 = 2 * t;             // this thread's column pair

    {   // load + pack inputs: thread -> (p = t>>6, k = t&63)
        int p = t >> 6, k = t & 63;
        xs2[p][k] = packf2(shift_bits[(b0 + p) * NBITS + k],
                           shift_bits[(b0 + p + 4) * NBITS + k]);
    }
    __syncthreads();

    {   // layer 1: cols (c0, c0+1), K=64
        ull a0[4], a1[4];
        #pragma unroll
        for (int p = 0; p < 4; p++) { a0[p] = 0; a1[p] = 0; }
        for (int k = 0; k < NBITS; k++) {
            float2 wv = ((const float2*)(sd_w1 + k * NH))[t];
            ull w0 = dupf(wv.x), w1 = dupf(wv.y);
            #pragma unroll
            for (int p = 0; p < 4; p++) {
                ull x = xs2[p][k];
                ffma2(a0[p], x, w0);
                ffma2(a1[p], x, w1);
            }
        }
        float2 bv = ((const float2*)sd_b1)[t];
        #pragma unroll
        for (int p = 0; p < 4; p++) {
            float2 v0 = unpf2(a0[p]), v1 = unpf2(a1[p]);
            hs2[p][c0]     = packf2(fmaxf(v0.x + bv.x, 0.f), fmaxf(v0.y + bv.x, 0.f));
            hs2[p][c0 + 1] = packf2(fmaxf(v1.x + bv.y, 0.f), fmaxf(v1.y + bv.y, 0.f));
        }
    }
    __syncthreads();

    {   // layer 2: K=512
        ull a0[4], a1[4];
        #pragma unroll
        for (int p = 0; p < 4; p++) { a0[p] = 0; a1[p] = 0; }
        for (int k = 0; k < NH; k++) {
            float2 wv = ((const float2*)(sd_w2 + k * NH))[t];
            ull w0 = dupf(wv.x), w1 = dupf(wv.y);
            #pragma unroll
            for (int p = 0; p < 4; p++) {
                ull h = hs2[p][k];
                ffma2(a0[p], h, w0);
                ffma2(a1[p], h, w1);
            }
        }
        float2 bv = ((const float2*)sd_b2)[t];
        #pragma unroll
        for (int p = 0; p < 4; p++) {
            float2 v0 = unpf2(a0[p]), v1 = unpf2(a1[p]);
            gs2[p][c0]     = packf2(fmaxf(v0.x + bv.x, 0.f), fmaxf(v0.y + bv.x, 0.f));
            gs2[p][c0 + 1] = packf2(fmaxf(v1.x + bv.y, 0.f), fmaxf(v1.y + bv.y, 0.f));
        }
    }
    __syncthreads();

    {   // layer 3: 8 rows x 64 cols = 512 outputs, 2 per thread
        int r = t >> 5, j = t & 31;
        const float* gview = (const float*)gs2;
        int lanesel = r >> 2, pp = r & 3;
        float acc0 = 0.f, acc1 = 0.f;
        for (int k = 0; k < NH; k++) {
            float gv = gview[(pp * NH + k) * 2 + lanesel];
            acc0 = fmaf(gv, sd_w3[k * NBITS + j],      acc0);
            acc1 = fmaf(gv, sd_w3[k * NBITS + j + 32], acc1);
        }
        lgs[r][j]      = acc0 + sd_b3[j];
        lgs[r][j + 32] = acc1 + sd_b3[j + 32];
    }
    __syncthreads();

    {   // softmax over 64: warp w -> row w
        int wr = t >> 5, l = t & 31;
        float v0 = lgs[wr][l], v1 = lgs[wr][l + 32];
        float m = fmaxf(v0, v1);
        #pragma unroll
        for (int o = 16; o > 0; o >>= 1) m = fmaxf(m, __shfl_xor_sync(0xffffffffu, m, o));
        float e0 = expf(v0 - m), e1 = expf(v1 - m);
        float s = e0 + e1;
        #pragma unroll
        for (int o = 16; o > 0; o >>= 1) s += __shfl_xor_sync(0xffffffffu, s, o);
        float inv = 1.f / s;
        sms[wr][l] = e0 * inv;
        sms[wr][l + 32] = e1 * inv;
    }
    __syncthreads();
    {   // pack softmax row pairs
        int p = t >> 6, k = t & 63;
        sms2[p][k] = packf2(sms[p][k], sms[p + 4][k]);
    }
    __syncthreads();

    {   // shift_part: K=64, cols (c0, c0+1)
        ull a0[4], a1[4];
        #pragma unroll
        for (int p = 0; p < 4; p++) { a0[p] = 0; a1[p] = 0; }
        for (int k = 0; k < NBITS; k++) {
            float2 wv = ((const float2*)(ix_w1 + (NBITS + k) * NH))[t];
            ull w0 = dupf(wv.x), w1 = dupf(wv.y);
            #pragma unroll
            for (int p = 0; p < 4; p++) {
                ull s = sms2[p][k];
                ffma2(a0[p], s, w0);
                ffma2(a1[p], s, w1);
            }
        }
        #pragma unroll
        for (int p = 0; p < 4; p++) {
            float2 v0 = unpf2(a0[p]), v1 = unpf2(a1[p]);
            g_sp[(b0 + p) * NH + c0]         = v0.x;
            g_sp[(b0 + p + 4) * NH + c0]     = v0.y;
            g_sp[(b0 + p) * NH + c0 + 1]     = v1.x;
            g_sp[(b0 + p + 4) * NH + c0 + 1] = v1.y;
        }
    }

    if (t < 128) {   // v_shift: K=64, cols (2t, 2t+1) of 256
        ull a0[4], a1[4];
        #pragma unroll
        for (int p = 0; p < 4; p++) { a0[p] = 0; a1[p] = 0; }
        for (int k = 0; k < NBITS; k++) {
            float2 wv = ((const float2*)(v_w1 + (NBITS + k) * NHV))[t];
            ull w0 = dupf(wv.x), w1 = dupf(wv.y);
            #pragma unroll
            for (int p = 0; p < 4; p++) {
                ull s = sms2[p][k];
                ffma2(a0[p], s, w0);
                ffma2(a1[p], s, w1);
            }
        }
        #pragma unroll
        for (int p = 0; p < 4; p++) {
            float2 v0 = unpf2(a0[p]), v1 = unpf2(a1[p]);
            g_vs[(b0 + p) * NHV + c0]         = v0.x;
            g_vs[(b0 + p + 4) * NHV + c0]     = v0.y;
            g_vs[(b0 + p) * NHV + c0 + 1]     = v1.x;
            g_vs[(b0 + p + 4) * NHV + c0 + 1] = v1.y;
        }
    }
}

// ---------------------------------------------------------------------------
// Kernel 2: FP8 mma.sync, M=64 (1 batch/CTA), 256 threads, 2 CTAs/SM.
// Warp grid 2m x 4n. Chunk loop fully unrolled (folds addresses -> less ALU).
// ---------------------------------------------------------------------------
__global__ __launch_bounds__(256, 2) void main_mma_kernel(
    const float* __restrict__ a_bits,
    const float* __restrict__ ix_w1, const float* __restrict__ ix_b1,
    const float* __restrict__ ix_b2, const float* __restrict__ ix_b3,
    const float* __restrict__ v_w1,  const float* __restrict__ v_b1,
    const float* __restrict__ v_w2,  const float* __restrict__ v_b2,
    float* __restrict__ out)
{
    extern __shared__ char bp[];
    float* b2s  = (float*)(bp + B2_OFF);   // prescaled x16
    float* b3s  = (float*)(bp + B3_OFF);
    float* ab_s = (float*)(bp + AB_OFF);
    float* vs_s = (float*)(bp + VS_OFF);
    float* vw2s = (float*)(bp + VW2_OFF);

    const int t    = threadIdx.x;
    const int lane = t & 31, w = t >> 5;
    const int g = lane >> 2, tg = lane & 3;
    const int mg = w & 1, ng = w >> 1;       // 2m x 4n warp grid
    const int b  = blockIdx.x;

    const uint32_t smb = smem_u32(bp);

    {   // prologue: W2 chunk 0
        #pragma unroll
        for (int i = 0; i < 4; i++) {
            int idx = t + i * 256;
            int row = idx >> 3, c16 = idx & 7;
            cp16(smb + W2_OFF + row * W2_STR + c16 * 16,
                 g_w2f8 + row * NH + c16 * 16);
        }
        asm volatile("cp.async.commit_group;" ::: "memory");
    }

    for (int i = t; i < NH; i += 256)
        b2s[i] = ix_b2[i] * SCALE;
    vs_s[t]  = g_vs[b * NHV + t] + v_b1[t];     // NHV == 256 == blockDim
    vw2s[t]  = v_w2[t];
    if (t < NBITS) { b3s[t] = ix_b3[t]; ab_s[t] = a_bits[b * NBITS + t]; }

    // h1 build: e4m3 (x16) [64 rows][512 k], stride 528 B
    #pragma unroll 4
    for (int i = 0; i < 32; i++) {
        int idx = t + i * 256;               // 0..8191 u32
        int mm = idx >> 7, qq = idx & 127;
        int k = qq * 4;
        float4 p  = *(const float4*)(ix_w1 + mm * NH + k);
        float4 s  = *(const float4*)(g_sp + b * NH + k);
        float4 bb = *(const float4*)(ix_b1 + k);
        float v0 = fmaxf(p.x + s.x + bb.x, 0.f) * SCALE;
        float v1 = fmaxf(p.y + s.y + bb.y, 0.f) * SCALE;
        float v2 = fmaxf(p.z + s.z + bb.z, 0.f) * SCALE;
        float v3 = fmaxf(p.w + s.w + bb.w, 0.f) * SCALE;
        *(uint32_t*)(bp + H1_OFF + mm * H1_STR + k) = pack_e4m3x4(v0, v1, v2, v3);
    }

    float lg[2][2][4];
    #pragma unroll
    for (int mt = 0; mt < 2; mt++)
        #pragma unroll
        for (int nt = 0; nt < 2; nt++)
            #pragma unroll
            for (int j2 = 0; j2 < 4; j2++) lg[mt][nt][j2] = 0.f;

    float acc[2][4][4];

    const uint32_t bfrag = (uint32_t)((lane & 7) * W2_STR + (lane >> 3) * 16);
    uint32_t h1a[2];
    h1a[0] = smb + H1_OFF + (uint32_t)((mg * 32 + (lane & 15)) * H1_STR + (lane >> 4) * 16);
    h1a[1] = h1a[0] + 16 * H1_STR;
    const uint32_t w3b = smb + W3_OFF + (uint32_t)(ng * 16 * W2_STR) + bfrag;

    #pragma unroll
    for (int c = 0; c < 16; c++) {
        const int nb = c >> 2, kb = c & 3;
        const int next = c + 1;
        if (next < 16) {
            int nnb = next >> 2, nkb = next & 3;
            const uint8_t* src = g_w2f8 + (nnb * 128) * NH + nkb * 128;
            uint32_t dstb = smb + W2_OFF + (next & 1) * W2_TILE;
            #pragma unroll
            for (int i = 0; i < 4; i++) {
                int idx = t + i * 256;
                int row = idx >> 3, c16 = idx & 7;
                cp16(dstb + row * W2_STR + c16 * 16, src + row * NH + c16 * 16);
            }
            if (nkb == 1) {
                #pragma unroll
                for (int i = 0; i < 2; i++) {
                    int idx = t + i * 256;
                    int row = idx >> 3, c16 = idx & 7;
                    cp16(smb + W3_OFF + row * W2_STR + c16 * 16,
                         g_w3f8 + row * NH + nnb * 128 + c16 * 16);
                }
            }
            asm volatile("cp.async.commit_group;" ::: "memory");
            asm volatile("cp.async.wait_group 1;" ::: "memory");
        } else {
            asm volatile("cp.async.wait_group 0;" ::: "memory");
        }
        __syncthreads();

        if (kb == 0) {
            #pragma unroll
            for (int mt = 0; mt < 2; mt++)
                #pragma unroll
                for (int nt = 0; nt < 4; nt++) {
                    acc[mt][nt][0] = 0.f; acc[mt][nt][1] = 0.f;
                    acc[mt][nt][2] = 0.f; acc[mt][nt][3] = 0.f;
                }
        }

        const uint32_t bufA = smb + W2_OFF + (c & 1) * W2_TILE;
        const uint32_t w2b = bufA + (uint32_t)(ng * 32 * W2_STR) + bfrag;
        const uint32_t akb = (uint32_t)(kb * 128);

        #pragma unroll
        for (int ks2 = 0; ks2 < 2; ks2++) {
            uint32_t Bv[4][4];
            #pragma unroll
            for (int nt = 0; nt < 4; nt++)
                ldm_x4(Bv[nt], w2b + nt * (8 * W2_STR) + ks2 * 64);
            uint32_t Am[2][2][4];
            #pragma unroll
            for (int mt = 0; mt < 2; mt++) {
                ldm_x4(Am[mt][0], h1a[mt] + akb + (2 * ks2)     * 32);
                ldm_x4(Am[mt][1], h1a[mt] + akb + (2 * ks2 + 1) * 32);
            }
            #pragma unroll
            for (int mt = 0; mt < 2; mt++)
                #pragma unroll
                for (int nt = 0; nt < 4; nt++) {
                    mma_fp8(acc[mt][nt], Am[mt][0], Bv[nt][0], Bv[nt][1]);
                    mma_fp8(acc[mt][nt], Am[mt][1], Bv[nt][2], Bv[nt][3]);
                }
        }

        if (kb == 3) {
            __syncthreads();   // bufA fully read -> reuse for h2 (e4m3 x16)
            #pragma unroll
            for (int mt = 0; mt < 2; mt++)
                #pragma unroll
                for (int nt = 0; nt < 4; nt++) {
                    int col = ng * 32 + nt * 8 + tg * 2;
                    float bb0 = b2s[nb * 128 + col], bb1 = b2s[nb * 128 + col + 1];
                    int r0 = mg * 32 + mt * 16 + g;
                    uint16_t p0 = pack_e4m3x2(
                        fmaxf(acc[mt][nt][0] * 0.0625f + bb0, 0.f),
                        fmaxf(acc[mt][nt][1] * 0.0625f + bb1, 0.f));
                    uint16_t p1 = pack_e4m3x2(
                        fmaxf(acc[mt][nt][2] * 0.0625f + bb0, 0.f),
                        fmaxf(acc[mt][nt][3] * 0.0625f + bb1, 0.f));
                    *(uint16_t*)(bp + (bufA - smb) + r0 * W2_STR + col) = p0;
                    *(uint16_t*)(bp + (bufA - smb) + (r0 + 8) * W2_STR + col) = p1;
                }
            __syncthreads();

            uint32_t a2b[2];
            a2b[0] = bufA + (uint32_t)((mg * 32 + (lane & 15)) * W2_STR + (lane >> 4) * 16);
            a2b[1] = a2b[0] + 16 * W2_STR;
            #pragma unroll
            for (int ks2 = 0; ks2 < 2; ks2++) {
                uint32_t B2v[2][4];
                #pragma unroll
                for (int nt = 0; nt < 2; nt++)
                    ldm_x4(B2v[nt], w3b + nt * (8 * W2_STR) + ks2 * 64);
                uint32_t A2[2][2][4];
                #pragma unroll
                for (int mt = 0; mt < 2; mt++) {
                    ldm_x4(A2[mt][0], a2b[mt] + (2 * ks2)     * 32);
                    ldm_x4(A2[mt][1], a2b[mt] + (2 * ks2 + 1) * 32);
                }
                #pragma unroll
                for (int mt = 0; mt < 2; mt++)
                    #pragma unroll
                    for (int nt = 0; nt < 2; nt++) {
                        mma_fp8(lg[mt][nt], A2[mt][0], B2v[nt][0], B2v[nt][1]);
                        mma_fp8(lg[mt][nt], A2[mt][1], B2v[nt][2], B2v[nt][3]);
                    }
            }
        }
        __syncthreads();
    }

    // logits -> smem (f32, stride 68), reusing W2 buffer 0
    float* lbuf = (float*)(bp + LG_OFF);
    #pragma unroll
    for (int mt = 0; mt < 2; mt++)
        #pragma unroll
        for (int nt = 0; nt < 2; nt++) {
            int col = ng * 16 + nt * 8 + tg * 2;
            int r0 = mg * 32 + mt * 16 + g;
            lbuf[r0 * 68 + col]     = lg[mt][nt][0];
            lbuf[r0 * 68 + col + 1] = lg[mt][nt][1];
            lbuf[(r0 + 8) * 68 + col]     = lg[mt][nt][2];
            lbuf[(r0 + 8) * 68 + col + 1] = lg[mt][nt][3];
        }
    __syncthreads();

    // epilogue: 4 threads per row (quad), 64 rows. lg = 256 x true logits.
    {
        const int row = t >> 2, tq = t & 3;
        float v[16];
        float mx = -1e30f;
        #pragma unroll
        for (int i = 0; i < 16; i++) {
            int col = i * 4 + tq;
            v[i] = lbuf[row * 68 + col] * INV_SC2 + b3s[col];
            mx = fmaxf(mx, v[i]);
        }
        mx = fmaxf(mx, __shfl_xor_sync(0xffffffffu, mx, 1));
        mx = fmaxf(mx, __shfl_xor_sync(0xffffffffu, mx, 2));

        float den = 0.f, num = 0.f;
        #pragma unroll
        for (int i = 0; i < 16; i++) {
            float e = expf(v[i] - mx);
            den += e;
            num = fmaf(e, ab_s[i * 4 + tq], num);
        }
        den += __shfl_xor_sync(0xffffffffu, den, 1);
        den += __shfl_xor_sync(0xffffffffu, den, 2);
        num += __shfl_xor_sync(0xffffffffu, num, 1);
        num += __shfl_xor_sync(0xffffffffu, num, 2);
        float pointed = num / den;

        const float* vrow = v_w1 + row * NHV;
        float acc2 = 0.f;
        #pragma unroll 8
        for (int jj = 0; jj < 64; jj++) {
            int j = jj * 4 + tq;
            float vh = fmaxf(vrow[j] + vs_s[j], 0.f);
            acc2 = fmaf(vh, vw2s[j], acc2);
        }
        acc2 += __shfl_xor_sync(0xffffffffu, acc2, 1);
        acc2 += __shfl_xor_sync(0xffffffffu, acc2, 2);
        if (tq == 0) {
            float vlog = acc2 + v_b2[0];
            out[b * NBITS + row] = pointed * (1.f / (1.f + expf(-vlog)));
        }
    }
}

extern "C" void kernel_launch(void* const* d_in, const int* in_sizes, int n_in,
                              void* d_out, int out_size)
{
    const float* a_bits     = (const float*)d_in[0];
    const float* shift_bits = (const float*)d_in[1];
    const float* sd_w1 = (const float*)d_in[2];
    const float* sd_b1 = (const float*)d_in[3];
    const float* sd_w2 = (const float*)d_in[4];
    const float* sd_b2 = (const float*)d_in[5];
    const float* sd_w3 = (const float*)d_in[6];
    const float* sd_b3 = (const float*)d_in[7];
    const float* ix_w1 = (const float*)d_in[8];
    const float* ix_b1 = (const float*)d_in[9];
    const float* ix_w2 = (const float*)d_in[10];
    const float* ix_b2 = (const float*)d_in[11];
    const float* ix_w3 = (const float*)d_in[12];
    const float* ix_b3 = (const float*)d_in[13];
    const float* v_w1  = (const float*)d_in[14];
    const float* v_b1  = (const float*)d_in[15];
    const float* v_w2  = (const float*)d_in[16];
    const float* v_b2  = (const float*)d_in[17];
    float* out = (float*)d_out;

    cudaFuncSetAttribute(main_mma_kernel,
                         cudaFuncAttributeMaxDynamicSharedMemorySize, SM_TOTAL);

    aux_kernel<<<544, 256>>>(shift_bits, sd_w1, sd_b1, sd_w2, sd_b2,
                             sd_w3, sd_b3, ix_w1, v_w1, ix_w2, ix_w3);
    main_mma_kernel<<<NB, 256, SM_TOTAL>>>(a_bits, ix_w1, ix_b1, ix_b2, ix_b3,
                                           v_w1, v_b1, v_w2, v_b2, out);
}

// round 14
// speedup vs baseline: 1.2500x; 1.0724x over previous
#include <cuda_runtime.h>
#include <cuda_bf16.h>
#include <math.h>
#include <stdint.h>

#define NB    2048
#define NBITS 64
#define NH    512
#define NHV   256

typedef unsigned long long ull;

__device__ float g_sp[NB * NH];
__device__ float g_vs[NB * NHV];
__device__ uint8_t g_w2f8[NH * NH];     // W2^T e4m3 (x16)  [n][k]
__device__ uint8_t g_w3f8[NBITS * NH];  // W3^T e4m3 (x16)  [n3][k]
__device__ int g_sync[257];             // [0]=prep count, [1+i]=shift block i done

__device__ __forceinline__ uint32_t smem_u32(const void* p) {
    uint32_t a;
    asm("{ .reg .u64 t; cvta.to.shared.u64 t, %1; cvt.u32.u64 %0, t; }"
        : "=r"(a) : "l"(p));
    return a;
}
__device__ __forceinline__ uint16_t pack_e4m3x2(float lo, float hi) {
    uint16_t r;
    asm("cvt.rn.satfinite.e4m3x2.f32 %0, %1, %2;" : "=h"(r) : "f"(hi), "f"(lo));
    return r;
}
__device__ __forceinline__ uint32_t pack_e4m3x4(float a, float b, float c, float d) {
    uint16_t lo = pack_e4m3x2(a, b);
    uint16_t hi = pack_e4m3x2(c, d);
    uint32_t r;
    asm("mov.b32 %0, {%1, %2};" : "=r"(r) : "h"(lo), "h"(hi));
    return r;
}
__device__ __forceinline__ void cp16(uint32_t dst, const void* src) {
    asm volatile("cp.async.cg.shared.global [%0], [%1], 16;"
                 :: "r"(dst), "l"(src) : "memory");
}
__device__ __forceinline__ void mma_fp8(float* c, const uint32_t* a,
                                        uint32_t b0, uint32_t b1) {
    asm volatile("mma.sync.aligned.m16n8k32.row.col.f32.e4m3.e4m3.f32 "
                 "{%0,%1,%2,%3}, {%4,%5,%6,%7}, {%8,%9}, {%0,%1,%2,%3};"
                 : "+f"(c[0]), "+f"(c[1]), "+f"(c[2]), "+f"(c[3])
                 : "r"(a[0]), "r"(a[1]), "r"(a[2]), "r"(a[3]),
                   "r"(b0), "r"(b1));
}
__device__ __forceinline__ void ldm_x4(uint32_t* r, uint32_t addr) {
    asm volatile("ldmatrix.sync.aligned.m8n8.x4.shared.b16 {%0,%1,%2,%3}, [%4];"
                 : "=r"(r[0]), "=r"(r[1]), "=r"(r[2]), "=r"(r[3]) : "r"(addr));
}
__device__ __forceinline__ void ffma2(ull& c, ull a, ull b) {
    asm("fma.rn.f32x2 %0, %1, %2, %0;" : "+l"(c) : "l"(a), "l"(b));
}
__device__ __forceinline__ ull dupf(float x) {
    ull r; asm("mov.b64 %0, {%1, %1};" : "=l"(r) : "f"(x)); return r;
}
__device__ __forceinline__ ull packf2(float x, float y) {
    ull r; asm("mov.b64 %0, {%1, %2};" : "=l"(r) : "f"(x), "f"(y)); return r;
}
__device__ __forceinline__ float2 unpf2(ull v) {
    float2 r; asm("mov.b64 {%0, %1}, %2;" : "=f"(r.x), "=f"(r.y) : "l"(v)); return r;
}

#define SCALE     16.0f
#define INV_SC2   (1.0f / 256.0f)

// SMEM layout (fp8, M=64 per CTA): total 84480 B -> 2 CTAs/SM
#define H1_OFF   0
#define H1_STR   528
#define W2_OFF   33792
#define W2_TILE  18432
#define W2_STR   144
#define W3_OFF   70656
#define B2_OFF   79872
#define B3_OFF   81920
#define AB_OFF   82176
#define VS_OFF   82432
#define VW2_OFF  83456
#define SM_TOTAL 84480
#define LG_OFF   W2_OFF

#define AUX_BLOCKS 544   // 256 shift + 256 W2 prep + 32 W3 prep

// ---------------------------------------------------------------------------
// Fused kernel: aux (blocks 0..543) + main (blocks 544..2591).
// Main blocks spin-wait on flags set by aux blocks (dispatched first).
// ---------------------------------------------------------------------------
__global__ __launch_bounds__(256, 2) void fused_kernel(
    const float* __restrict__ shift_bits,
    const float* __restrict__ sd_w1, const float* __restrict__ sd_b1,
    const float* __restrict__ sd_w2, const float* __restrict__ sd_b2,
    const float* __restrict__ sd_w3, const float* __restrict__ sd_b3,
    const float* __restrict__ ix_w1, const float* __restrict__ v_w1,
    const float* __restrict__ ix_w2, const float* __restrict__ ix_w3,
    const float* __restrict__ a_bits,
    const float* __restrict__ ix_b1, const float* __restrict__ ix_b2,
    const float* __restrict__ ix_b3,
    const float* __restrict__ v_b1,  const float* __restrict__ v_w2,
    const float* __restrict__ v_b2,
    float* __restrict__ out)
{
    extern __shared__ char bp[];
    const int bid = blockIdx.x;
    const int t   = threadIdx.x;

    // =======================================================================
    // AUX: weight prep blocks
    // =======================================================================
    if (bid >= 256 && bid < AUX_BLOCKS) {
        if (bid < 512) {                       // W2: transpose + scale + fp8
            int idx = (bid - 256) * 256 + t;
            int n = idx >> 7, k4 = (idx & 127) * 4;
            float w0 = ix_w2[(k4 + 0) * NH + n] * SCALE;
            float w1 = ix_w2[(k4 + 1) * NH + n] * SCALE;
            float w2v = ix_w2[(k4 + 2) * NH + n] * SCALE;
            float w3v = ix_w2[(k4 + 3) * NH + n] * SCALE;
            ((uint32_t*)g_w2f8)[n * 128 + (idx & 127)] = pack_e4m3x4(w0, w1, w2v, w3v);
        } else {                               // W3
            int idx = (bid - 512) * 256 + t;
            int n3 = idx >> 7, k4g = idx & 127;
            int k4 = k4g * 4;
            float w0 = ix_w3[(k4 + 0) * NBITS + n3] * SCALE;
            float w1 = ix_w3[(k4 + 1) * NBITS + n3] * SCALE;
            float w2v = ix_w3[(k4 + 2) * NBITS + n3] * SCALE;
            float w3v = ix_w3[(k4 + 3) * NBITS + n3] * SCALE;
            ((uint32_t*)g_w3f8)[n3 * 128 + k4g] = pack_e4m3x4(w0, w1, w2v, w3v);
        }
        __threadfence();
        __syncthreads();
        if (t == 0) atomicAdd(&g_sync[0], 1);
        return;
    }

    // =======================================================================
    // AUX: shift MLP blocks (0..255), 8 batch rows each, FFMA2 row-pair packed
    // Scratch aliased into dynamic smem (40KB < 84.5KB).
    // =======================================================================
    if (bid < 256) {
        ull   (*xs2)[NBITS]  = (ull(*)[NBITS]) (bp + 0);
        ull   (*hs2)[NH]     = (ull(*)[NH])    (bp + 2048);
        ull   (*gs2)[NH]     = (ull(*)[NH])    (bp + 18432);
        float (*lgs)[NBITS]  = (float(*)[NBITS])(bp + 34816);
        float (*sms)[NBITS]  = (float(*)[NBITS])(bp + 36864);
        ull   (*sms2)[NBITS] = (ull(*)[NBITS]) (bp + 38912);

        const int b0 = bid * 8;
        const int c0 = 2 * t;

        {   // load + pack inputs
            int p = t >> 6, k = t & 63;
            xs2[p][k] = packf2(shift_bits[(b0 + p) * NBITS + k],
                               shift_bits[(b0 + p + 4) * NBITS + k]);
        }
        __syncthreads();

        {   // layer 1: K=64
            ull a0[4], a1[4];
            #pragma unroll
            for (int p = 0; p < 4; p++) { a0[p] = 0; a1[p] = 0; }
            for (int k = 0; k < NBITS; k++) {
                float2 wv = ((const float2*)(sd_w1 + k * NH))[t];
                ull w0 = dupf(wv.x), w1 = dupf(wv.y);
                #pragma unroll
                for (int p = 0; p < 4; p++) {
                    ull x = xs2[p][k];
                    ffma2(a0[p], x, w0);
                    ffma2(a1[p], x, w1);
                }
            }
            float2 bv = ((const float2*)sd_b1)[t];
            #pragma unroll
            for (int p = 0; p < 4; p++) {
                float2 v0 = unpf2(a0[p]), v1 = unpf2(a1[p]);
                hs2[p][c0]     = packf2(fmaxf(v0.x + bv.x, 0.f), fmaxf(v0.y + bv.x, 0.f));
                hs2[p][c0 + 1] = packf2(fmaxf(v1.x + bv.y, 0.f), fmaxf(v1.y + bv.y, 0.f));
            }
        }
        __syncthreads();

        {   // layer 2: K=512
            ull a0[4], a1[4];
            #pragma unroll
            for (int p = 0; p < 4; p++) { a0[p] = 0; a1[p] = 0; }
            for (int k = 0; k < NH; k++) {
                float2 wv = ((const float2*)(sd_w2 + k * NH))[t];
                ull w0 = dupf(wv.x), w1 = dupf(wv.y);
                #pragma unroll
                for (int p = 0; p < 4; p++) {
                    ull h = hs2[p][k];
                    ffma2(a0[p], h, w0);
                    ffma2(a1[p], h, w1);
                }
            }
            float2 bv = ((const float2*)sd_b2)[t];
            #pragma unroll
            for (int p = 0; p < 4; p++) {
                float2 v0 = unpf2(a0[p]), v1 = unpf2(a1[p]);
                gs2[p][c0]     = packf2(fmaxf(v0.x + bv.x, 0.f), fmaxf(v0.y + bv.x, 0.f));
                gs2[p][c0 + 1] = packf2(fmaxf(v1.x + bv.y, 0.f), fmaxf(v1.y + bv.y, 0.f));
            }
        }
        __syncthreads();

        {   // layer 3
            int r = t >> 5, j = t & 31;
            const float* gview = (const float*)gs2;
            int lanesel = r >> 2, pp = r & 3;
            float acc0 = 0.f, acc1 = 0.f;
            for (int k = 0; k < NH; k++) {
                float gv = gview[(pp * NH + k) * 2 + lanesel];
                acc0 = fmaf(gv, sd_w3[k * NBITS + j],      acc0);
                acc1 = fmaf(gv, sd_w3[k * NBITS + j + 32], acc1);
            }
            lgs[r][j]      = acc0 + sd_b3[j];
            lgs[r][j + 32] = acc1 + sd_b3[j + 32];
        }
        __syncthreads();

        {   // softmax over 64: warp w -> row w
            int wr = t >> 5, l = t & 31;
            float v0 = lgs[wr][l], v1 = lgs[wr][l + 32];
            float m = fmaxf(v0, v1);
            #pragma unroll
            for (int o = 16; o > 0; o >>= 1) m = fmaxf(m, __shfl_xor_sync(0xffffffffu, m, o));
            float e0 = expf(v0 - m), e1 = expf(v1 - m);
            float s = e0 + e1;
            #pragma unroll
            for (int o = 16; o > 0; o >>= 1) s += __shfl_xor_sync(0xffffffffu, s, o);
            float inv = 1.f / s;
            sms[wr][l] = e0 * inv;
            sms[wr][l + 32] = e1 * inv;
        }
        __syncthreads();
        {   // pack softmax row pairs
            int p = t >> 6, k = t & 63;
            sms2[p][k] = packf2(sms[p][k], sms[p + 4][k]);
        }
        __syncthreads();

        {   // shift_part
            ull a0[4], a1[4];
            #pragma unroll
            for (int p = 0; p < 4; p++) { a0[p] = 0; a1[p] = 0; }
            for (int k = 0; k < NBITS; k++) {
                float2 wv = ((const float2*)(ix_w1 + (NBITS + k) * NH))[t];
                ull w0 = dupf(wv.x), w1 = dupf(wv.y);
                #pragma unroll
                for (int p = 0; p < 4; p++) {
                    ull s = sms2[p][k];
                    ffma2(a0[p], s, w0);
                    ffma2(a1[p], s, w1);
                }
            }
            #pragma unroll
            for (int p = 0; p < 4; p++) {
                float2 v0 = unpf2(a0[p]), v1 = unpf2(a1[p]);
                g_sp[(b0 + p) * NH + c0]         = v0.x;
                g_sp[(b0 + p + 4) * NH + c0]     = v0.y;
                g_sp[(b0 + p) * NH + c0 + 1]     = v1.x;
                g_sp[(b0 + p + 4) * NH + c0 + 1] = v1.y;
            }
        }

        if (t < 128) {   // v_shift
            ull a0[4], a1[4];
            #pragma unroll
            for (int p = 0; p < 4; p++) { a0[p] = 0; a1[p] = 0; }
            for (int k = 0; k < NBITS; k++) {
                float2 wv = ((const float2*)(v_w1 + (NBITS + k) * NHV))[t];
                ull w0 = dupf(wv.x), w1 = dupf(wv.y);
                #pragma unroll
                for (int p = 0; p < 4; p++) {
                    ull s = sms2[p][k];
                    ffma2(a0[p], s, w0);
                    ffma2(a1[p], s, w1);
                }
            }
            #pragma unroll
            for (int p = 0; p < 4; p++) {
                float2 v0 = unpf2(a0[p]), v1 = unpf2(a1[p]);
                g_vs[(b0 + p) * NHV + c0]         = v0.x;
                g_vs[(b0 + p + 4) * NHV + c0]     = v0.y;
                g_vs[(b0 + p) * NHV + c0 + 1]     = v1.x;
                g_vs[(b0 + p + 4) * NHV + c0 + 1] = v1.y;
            }
        }

        __threadfence();
        __syncthreads();
        if (t == 0) atomicExch(&g_sync[1 + bid], 1);
        return;
    }

    // =======================================================================
    // MAIN: FP8 mma.sync chain, batch b = bid - 544. 2 CTAs/SM.
    // =======================================================================
    const int b = bid - AUX_BLOCKS;

    float* b2s  = (float*)(bp + B2_OFF);
    float* b3s  = (float*)(bp + B3_OFF);
    float* ab_s = (float*)(bp + AB_OFF);
    float* vs_s = (float*)(bp + VS_OFF);
    float* vw2s = (float*)(bp + VW2_OFF);

    const int lane = t & 31, w = t >> 5;
    const int g = lane >> 2, tg = lane & 3;
    const int mg = w & 1, ng = w >> 1;       // 2m x 4n warp grid
    const uint32_t smb = smem_u32(bp);

    // independent staging first (no aux deps)
    for (int i = t; i < NH; i += 256)
        b2s[i] = ix_b2[i] * SCALE;
    vw2s[t] = v_w2[t];
    if (t < NBITS) { b3s[t] = ix_b3[t]; ab_s[t] = a_bits[b * NBITS + t]; }

    // wait for aux: prep complete + this batch's shift block done
    if (t == 0) {
        volatile int* sy = g_sync;
        while (sy[0] < 288) __nanosleep(200);
        while (sy[1 + (b >> 3)] == 0) __nanosleep(100);
    }
    __syncthreads();
    __threadfence();

    {   // prologue: W2 chunk 0
        #pragma unroll
        for (int i = 0; i < 4; i++) {
            int idx = t + i * 256;
            int row = idx >> 3, c16 = idx & 7;
            cp16(smb + W2_OFF + row * W2_STR + c16 * 16,
                 g_w2f8 + row * NH + c16 * 16);
        }
        asm volatile("cp.async.commit_group;" ::: "memory");
    }
    vs_s[t] = g_vs[b * NHV + t] + v_b1[t];

    // h1 build: e4m3 (x16) [64 rows][512 k], stride 528 B
    #pragma unroll 4
    for (int i = 0; i < 32; i++) {
        int idx = t + i * 256;
        int mm = idx >> 7, qq = idx & 127;
        int k = qq * 4;
        float4 p  = *(const float4*)(ix_w1 + mm * NH + k);
        float4 s  = *(const float4*)(g_sp + b * NH + k);
        float4 bb = *(const float4*)(ix_b1 + k);
        float v0 = fmaxf(p.x + s.x + bb.x, 0.f) * SCALE;
        float v1 = fmaxf(p.y + s.y + bb.y, 0.f) * SCALE;
        float v2 = fmaxf(p.z + s.z + bb.z, 0.f) * SCALE;
        float v3 = fmaxf(p.w + s.w + bb.w, 0.f) * SCALE;
        *(uint32_t*)(bp + H1_OFF + mm * H1_STR + k) = pack_e4m3x4(v0, v1, v2, v3);
    }

    float lg[2][2][4];
    #pragma unroll
    for (int mt = 0; mt < 2; mt++)
        #pragma unroll
        for (int nt = 0; nt < 2; nt++)
            #pragma unroll
            for (int j2 = 0; j2 < 4; j2++) lg[mt][nt][j2] = 0.f;

    float acc[2][4][4];

    const uint32_t bfrag = (uint32_t)((lane & 7) * W2_STR + (lane >> 3) * 16);
    uint32_t h1a[2];
    h1a[0] = smb + H1_OFF + (uint32_t)((mg * 32 + (lane & 15)) * H1_STR + (lane >> 4) * 16);
    h1a[1] = h1a[0] + 16 * H1_STR;
    const uint32_t w3b = smb + W3_OFF + (uint32_t)(ng * 16 * W2_STR) + bfrag;

    #pragma unroll
    for (int c = 0; c < 16; c++) {
        const int nb = c >> 2, kb = c & 3;
        const int next = c + 1;
        if (next < 16) {
            int nnb = next >> 2, nkb = next & 3;
            const uint8_t* src = g_w2f8 + (nnb * 128) * NH + nkb * 128;
            uint32_t dstb = smb + W2_OFF + (next & 1) * W2_TILE;
            #pragma unroll
            for (int i = 0; i < 4; i++) {
                int idx = t + i * 256;
                int row = idx >> 3, c16 = idx & 7;
                cp16(dstb + row * W2_STR + c16 * 16, src + row * NH + c16 * 16);
            }
            if (nkb == 1) {
                #pragma unroll
                for (int i = 0; i < 2; i++) {
                    int idx = t + i * 256;
                    int row = idx >> 3, c16 = idx & 7;
                    cp16(smb + W3_OFF + row * W2_STR + c16 * 16,
                         g_w3f8 + row * NH + nnb * 128 + c16 * 16);
                }
            }
            asm volatile("cp.async.commit_group;" ::: "memory");
            asm volatile("cp.async.wait_group 1;" ::: "memory");
        } else {
            asm volatile("cp.async.wait_group 0;" ::: "memory");
        }
        __syncthreads();

        if (kb == 0) {
            #pragma unroll
            for (int mt = 0; mt < 2; mt++)
                #pragma unroll
                for (int nt = 0; nt < 4; nt++) {
                    acc[mt][nt][0] = 0.f; acc[mt][nt][1] = 0.f;
                    acc[mt][nt][2] = 0.f; acc[mt][nt][3] = 0.f;
                }
        }

        const uint32_t bufA = smb + W2_OFF + (c & 1) * W2_TILE;
        const uint32_t w2b = bufA + (uint32_t)(ng * 32 * W2_STR) + bfrag;
        const uint32_t akb = (uint32_t)(kb * 128);

        #pragma unroll
        for (int ks2 = 0; ks2 < 2; ks2++) {
            uint32_t Bv[4][4];
            #pragma unroll
            for (int nt = 0; nt < 4; nt++)
                ldm_x4(Bv[nt], w2b + nt * (8 * W2_STR) + ks2 * 64);
            uint32_t Am[2][2][4];
            #pragma unroll
            for (int mt = 0; mt < 2; mt++) {
                ldm_x4(Am[mt][0], h1a[mt] + akb + (2 * ks2)     * 32);
                ldm_x4(Am[mt][1], h1a[mt] + akb + (2 * ks2 + 1) * 32);
            }
            #pragma unroll
            for (int mt = 0; mt < 2; mt++)
                #pragma unroll
                for (int nt = 0; nt < 4; nt++) {
                    mma_fp8(acc[mt][nt], Am[mt][0], Bv[nt][0], Bv[nt][1]);
                    mma_fp8(acc[mt][nt], Am[mt][1], Bv[nt][2], Bv[nt][3]);
                }
        }

        if (kb == 3) {
            __syncthreads();   // bufA fully read -> reuse for h2 (e4m3 x16)
            #pragma unroll
            for (int mt = 0; mt < 2; mt++)
                #pragma unroll
                for (int nt = 0; nt < 4; nt++) {
                    int col = ng * 32 + nt * 8 + tg * 2;
                    float bb0 = b2s[nb * 128 + col], bb1 = b2s[nb * 128 + col + 1];
                    int r0 = mg * 32 + mt * 16 + g;
                    uint16_t p0 = pack_e4m3x2(
                        fmaxf(acc[mt][nt][0] * 0.0625f + bb0, 0.f),
                        fmaxf(acc[mt][nt][1] * 0.0625f + bb1, 0.f));
                    uint16_t p1 = pack_e4m3x2(
                        fmaxf(acc[mt][nt][2] * 0.0625f + bb0, 0.f),
                        fmaxf(acc[mt][nt][3] * 0.0625f + bb1, 0.f));
                    *(uint16_t*)(bp + (bufA - smb) + r0 * W2_STR + col) = p0;
                    *(uint16_t*)(bp + (bufA - smb) + (r0 + 8) * W2_STR + col) = p1;
                }
            __syncthreads();

            uint32_t a2b[2];
            a2b[0] = bufA + (uint32_t)((mg * 32 + (lane & 15)) * W2_STR + (lane >> 4) * 16);
            a2b[1] = a2b[0] + 16 * W2_STR;
            #pragma unroll
            for (int ks2 = 0; ks2 < 2; ks2++) {
                uint32_t B2v[2][4];
                #pragma unroll
                for (int nt = 0; nt < 2; nt++)
                    ldm_x4(B2v[nt], w3b + nt * (8 * W2_STR) + ks2 * 64);
                uint32_t A2[2][2][4];
                #pragma unroll
                for (int mt = 0; mt < 2; mt++) {
                    ldm_x4(A2[mt][0], a2b[mt] + (2 * ks2)     * 32);
                    ldm_x4(A2[mt][1], a2b[mt] + (2 * ks2 + 1) * 32);
                }
                #pragma unroll
                for (int mt = 0; mt < 2; mt++)
                    #pragma unroll
                    for (int nt = 0; nt < 2; nt++) {
                        mma_fp8(lg[mt][nt], A2[mt][0], B2v[nt][0], B2v[nt][1]);
                        mma_fp8(lg[mt][nt], A2[mt][1], B2v[nt][2], B2v[nt][3]);
                    }
            }
        }
        __syncthreads();
    }

    // logits -> smem (f32, stride 68), reusing W2 buffer 0
    float* lbuf = (float*)(bp + LG_OFF);
    #pragma unroll
    for (int mt = 0; mt < 2; mt++)
        #pragma unroll
        for (int nt = 0; nt < 2; nt++) {
            int col = ng * 16 + nt * 8 + tg * 2;
            int r0 = mg * 32 + mt * 16 + g;
            lbuf[r0 * 68 + col]     = lg[mt][nt][0];
            lbuf[r0 * 68 + col + 1] = lg[mt][nt][1];
            lbuf[(r0 + 8) * 68 + col]     = lg[mt][nt][2];
            lbuf[(r0 + 8) * 68 + col + 1] = lg[mt][nt][3];
        }
    __syncthreads();

    // epilogue: 4 threads per row (quad), 64 rows. lg = 256 x true logits.
    {
        const int row = t >> 2, tq = t & 3;
        float v[16];
        float mx = -1e30f;
        #pragma unroll
        for (int i = 0; i < 16; i++) {
            int col = i * 4 + tq;
            v[i] = lbuf[row * 68 + col] * INV_SC2 + b3s[col];
            mx = fmaxf(mx, v[i]);
        }
        mx = fmaxf(mx, __shfl_xor_sync(0xffffffffu, mx, 1));
        mx = fmaxf(mx, __shfl_xor_sync(0xffffffffu, mx, 2));

        float den = 0.f, num = 0.f;
        #pragma unroll
        for (int i = 0; i < 16; i++) {
            float e = expf(v[i] - mx);
            den += e;
            num = fmaf(e, ab_s[i * 4 + tq], num);
        }
        den += __shfl_xor_sync(0xffffffffu, den, 1);
        den += __shfl_xor_sync(0xffffffffu, den, 2);
        num += __shfl_xor_sync(0xffffffffu, num, 1);
        num += __shfl_xor_sync(0xffffffffu, num, 2);
        float pointed = num / den;

        const float* vrow = v_w1 + row * NHV;
        float acc2 = 0.f;
        #pragma unroll 8
        for (int jj = 0; jj < 64; jj++) {
            int j = jj * 4 + tq;
            float vh = fmaxf(vrow[j] + vs_s[j], 0.f);
            acc2 = fmaf(vh, vw2s[j], acc2);
        }
        acc2 += __shfl_xor_sync(0xffffffffu, acc2, 1);
        acc2 += __shfl_xor_sync(0xffffffffu, acc2, 2);
        if (tq == 0) {
            float vlog = acc2 + v_b2[0];
            out[b * NBITS + row] = pointed * (1.f / (1.f + expf(-vlog)));
        }
    }
}

extern "C" void kernel_launch(void* const* d_in, const int* in_sizes, int n_in,
                              void* d_out, int out_size)
{
    const float* a_bits     = (const float*)d_in[0];
    const float* shift_bits = (const float*)d_in[1];
    const float* sd_w1 = (const float*)d_in[2];
    const float* sd_b1 = (const float*)d_in[3];
    const float* sd_w2 = (const float*)d_in[4];
    const float* sd_b2 = (const float*)d_in[5];
    const float* sd_w3 = (const float*)d_in[6];
    const float* sd_b3 = (const float*)d_in[7];
    const float* ix_w1 = (const float*)d_in[8];
    const float* ix_b1 = (const float*)d_in[9];
    const float* ix_w2 = (const float*)d_in[10];
    const float* ix_b2 = (const float*)d_in[11];
    const float* ix_w3 = (const float*)d_in[12];
    const float* ix_b3 = (const float*)d_in[13];
    const float* v_w1  = (const float*)d_in[14];
    const float* v_b1  = (const float*)d_in[15];
    const float* v_w2  = (const float*)d_in[16];
    const float* v_b2  = (const float*)d_in[17];
    float* out = (float*)d_out;

    cudaFuncSetAttribute(fused_kernel,
                         cudaFuncAttributeMaxDynamicSharedMemorySize, SM_TOTAL);

    // zero the sync flags (graph-capturable, no allocation)
    void* sync_ptr = nullptr;
    cudaGetSymbolAddress(&sync_ptr, g_sync);
    cudaMemsetAsync(sync_ptr, 0, sizeof(int) * 257);

    fused_kernel<<<AUX_BLOCKS + NB, 256, SM_TOTAL>>>(
        shift_bits, sd_w1, sd_b1, sd_w2, sd_b2, sd_w3, sd_b3,
        ix_w1, v_w1, ix_w2, ix_w3,
        a_bits, ix_b1, ix_b2, ix_b3, v_b1, v_w2, v_b2, out);
}